// round 9
// baseline (speedup 1.0000x reference)
#include <cuda_runtime.h>
#include <cuda_bf16.h>
#include <math.h>

// Problem constants
#define LNUM 4
#define DD   256
#define HH   8
#define INNER 2048
#define MM   1024
#define BB   8
#define NN_  1024
#define ROWS (BB*NN_)       // 8192
#define QKV_N (3*INNER)     // 6144
#define SCALE_ 0.0625f

// ---------------- device scratch ----------------
__device__ float g_h[(size_t)ROWS*DD];
__device__ float g_qkv[(size_t)ROWS*QKV_N];
__device__ float g_attn[(size_t)ROWS*INNER];
__device__ float g_mlp[(size_t)ROWS*MM];

__device__ __forceinline__ unsigned f2tf32(float x) {
    unsigned r;
    asm("cvt.rna.tf32.f32 %0, %1;" : "=r"(r) : "f"(x));
    return r;
}
__device__ __forceinline__ float rnd32(float x) {
    return __uint_as_float(f2tf32(x));
}

// ---------------- LayerNorm: warp per row, outputs tf32-rounded ------------
__global__ void ln_kernel(const float* __restrict__ x,
                          const float* __restrict__ g,
                          const float* __restrict__ b,
                          float* __restrict__ out) {
    const int row  = blockIdx.x*8 + (threadIdx.x >> 5);
    const int lane = threadIdx.x & 31;
    const float* px = x + (size_t)row*DD;
    float4 a = *reinterpret_cast<const float4*>(px + lane*4);
    float4 c = *reinterpret_cast<const float4*>(px + 128 + lane*4);
    float s1 = a.x+a.y+a.z+a.w + c.x+c.y+c.z+c.w;
    float s2 = a.x*a.x+a.y*a.y+a.z*a.z+a.w*a.w
             + c.x*c.x+c.y*c.y+c.z*c.z+c.w*c.w;
    #pragma unroll
    for (int o = 16; o > 0; o >>= 1) {
        s1 += __shfl_xor_sync(0xffffffffu, s1, o);
        s2 += __shfl_xor_sync(0xffffffffu, s2, o);
    }
    const float mu = s1 * (1.0f/DD);
    const float rs = rsqrtf(s2 * (1.0f/DD) - mu*mu + 1e-5f);
    float4 g0 = *reinterpret_cast<const float4*>(g + lane*4);
    float4 g1 = *reinterpret_cast<const float4*>(g + 128 + lane*4);
    float4 b0 = *reinterpret_cast<const float4*>(b + lane*4);
    float4 b1 = *reinterpret_cast<const float4*>(b + 128 + lane*4);
    float* po = out + (size_t)row*DD;
    *reinterpret_cast<float4*>(po + lane*4) = make_float4(
        rnd32((a.x-mu)*rs*g0.x + b0.x), rnd32((a.y-mu)*rs*g0.y + b0.y),
        rnd32((a.z-mu)*rs*g0.z + b0.z), rnd32((a.w-mu)*rs*g0.w + b0.w));
    *reinterpret_cast<float4*>(po + 128 + lane*4) = make_float4(
        rnd32((c.x-mu)*rs*g1.x + b1.x), rnd32((c.y-mu)*rs*g1.y + b1.y),
        rnd32((c.z-mu)*rs*g1.z + b1.z), rnd32((c.w-mu)*rs*g1.w + b1.w));
}

// ---------------- fused flash attention (no-max softmax) -------------------
// Per block: 64 q-rows of one (b,h). Loops 8 KV tiles of 128 keys.
//   S = Q @ K^T (cp.async + ldmatrix), P = round(exp(SCALE*S)) -> smem,
//   O += P @ V (V reg-staged), rowsum in regs; final O/rowsum -> g_attn.
// Dynamic smem layout (bytes):
//   Qs 2x64x128   @ 0       (16384)
//   Ks 2x128x128  @ 16384   (32768)
//   Vs 2x256x128  @ 49152   (65536)
//   Ps 64x512     @ 114688  (32768)
//   redS 8x64 f   @ 147456  (2048)
//   rowTot 64 f   @ 149504  (256)
#define FL_SMEM 149760

__global__ void __launch_bounds__(512, 1)
flash_attn(const float* __restrict__ qkv, float* __restrict__ attn)
{
    extern __shared__ char sm[];
    const int bh = blockIdx.z;
    const int bb = bh >> 3, hh = bh & 7;
    const int q0 = blockIdx.y * 64;
    const float* Qp = qkv + (size_t)bb*NN_*QKV_N + hh*DD;
    const float* Kp = Qp + INNER;
    const float* Vp = Qp + 2*INNER;

    const int tid  = threadIdx.x;
    const int lane = tid & 31, wid = tid >> 5;
    const int g = lane >> 2, t4 = lane & 3;

    const unsigned smB = (unsigned)__cvta_generic_to_shared(sm);
    const unsigned qsB = smB;
    const unsigned ksB = smB + 16384;
    const unsigned vsB = smB + 49152;
    const unsigned psB = smB + 114688;
    float* redS   = (float*)(sm + 147456);
    float* rowTot = (float*)(sm + 149504);

    // ldmatrix lane mapping (validated in gemm_tf32)
    const int ami   = lane >> 3;
    const int aHalf = ami >> 1;
    const int aRoff = ((ami & 1) << 3) + (lane & 7);
    const int bHalf = (lane >> 3) & 1;
    const int bRoff = ((lane >> 4) << 3) + (lane & 7);

    // S-phase warp map: 2 (rows) x 8 (col-16)
    const int sr = wid & 1, sc = wid >> 1;
    int aMs[2]; aMs[0] = sr*32 + aRoff; aMs[1] = sr*32 + 16 + aRoff;
    const int bNs = sc*16 + bRoff;

    // PV-phase warp map: 4 (rows-16) x 4 (col-64)
    const int pr = wid & 3, pc = wid >> 2;
    const int aMp = pr*16 + aRoff;
    int bNp[4];
    #pragma unroll
    for (int nf = 0; nf < 4; nf++) bNp[nf] = pc*64 + nf*16 + bRoff;

    // QK cp.async loader geometry
    const int rQ = tid >> 3;            // 0..63
    const int cQ = tid & 7;
    const float* qSrc = Qp + (size_t)(q0 + rQ)*QKV_N + cQ*4;
    const unsigned csw = (unsigned)((cQ ^ (rQ & 7))*16);
    const unsigned qDst  = qsB + rQ*128 + csw;
    const unsigned kDst0 = ksB + rQ*128 + csw;
    const unsigned kDst1 = ksB + (rQ+64)*128 + csw;   // (rQ+64)&7 == rQ&7

    // V loader geometry (NN reg-staged)
    const int nV  = tid & 255;
    const int kbV = (tid >> 8) * 16;
    const unsigned vDst = vsB + nV*128;

    float acc_o[8][4] = {};
    float rsum[2][2]  = {};

    for (int jt = 0; jt < 8; jt++) {
        const int kv0 = jt * 128;
        __syncthreads();                      // Ps free from prev PV phase

        // ================= S phase =================
        float acc_s[2][2][4] = {};
        auto issueQK = [&](int ch, int buf) {
            const float* q  = qSrc + ch*32;
            const float* k0 = Kp + (size_t)(kv0 + rQ)*QKV_N + cQ*4 + ch*32;
            const float* k1 = k0 + (size_t)64*QKV_N;
            asm volatile("cp.async.cg.shared.global [%0], [%1], 16;"
                         :: "r"(qDst + buf*8192), "l"(q));
            asm volatile("cp.async.cg.shared.global [%0], [%1], 16;"
                         :: "r"(kDst0 + buf*16384), "l"(k0));
            asm volatile("cp.async.cg.shared.global [%0], [%1], 16;"
                         :: "r"(kDst1 + buf*16384), "l"(k1));
            asm volatile("cp.async.commit_group;");
        };
        issueQK(0, 0);
        asm volatile("cp.async.wait_group 0;");
        __syncthreads();
        for (int ch = 0; ch < 8; ch++) {
            const int buf = ch & 1;
            const bool more = ch < 7;
            if (more) issueQK(ch + 1, buf ^ 1);
            const unsigned qB = qsB + buf*8192;
            const unsigned kB = ksB + buf*16384;
            #pragma unroll
            for (int k8 = 0; k8 < 4; k8++) {
                uint4 af[2], bf;
                #pragma unroll
                for (int mf = 0; mf < 2; mf++) {
                    unsigned addr = qB + aMs[mf]*128
                                  + ((((k8<<1)+aHalf) ^ (aMs[mf]&7)) << 4);
                    asm volatile(
                        "ldmatrix.sync.aligned.m8n8.x4.shared.b16 {%0,%1,%2,%3}, [%4];"
                        : "=r"(af[mf].x), "=r"(af[mf].y), "=r"(af[mf].z), "=r"(af[mf].w)
                        : "r"(addr));
                }
                {
                    unsigned addr = kB + bNs*128
                                  + ((((k8<<1)+bHalf) ^ (bNs&7)) << 4);
                    asm volatile(
                        "ldmatrix.sync.aligned.m8n8.x4.shared.b16 {%0,%1,%2,%3}, [%4];"
                        : "=r"(bf.x), "=r"(bf.y), "=r"(bf.z), "=r"(bf.w)
                        : "r"(addr));
                }
                unsigned bp[2][2] = {{bf.x, bf.y}, {bf.z, bf.w}};
                #pragma unroll
                for (int mf = 0; mf < 2; mf++)
                    #pragma unroll
                    for (int n = 0; n < 2; n++)
                        asm volatile(
                            "mma.sync.aligned.m16n8k8.row.col.f32.tf32.tf32.f32 "
                            "{%0,%1,%2,%3}, {%4,%5,%6,%7}, {%8,%9}, {%0,%1,%2,%3};"
                            : "+f"(acc_s[mf][n][0]), "+f"(acc_s[mf][n][1]),
                              "+f"(acc_s[mf][n][2]), "+f"(acc_s[mf][n][3])
                            : "r"(af[mf].x), "r"(af[mf].y), "r"(af[mf].z), "r"(af[mf].w),
                              "r"(bp[n][0]), "r"(bp[n][1]));
            }
            if (more) {
                asm volatile("cp.async.wait_group 0;");
                __syncthreads();
            }
        }

        // ======= exp + P store (ldmatrix layout) + rowsum =======
        #pragma unroll
        for (int mf = 0; mf < 2; mf++)
            #pragma unroll
            for (int n = 0; n < 2; n++)
                #pragma unroll
                for (int h = 0; h < 2; h++) {
                    const int row = sr*32 + mf*16 + h*8 + g;
                    const int col = sc*16 + n*8 + 2*t4;
                    float p0 = rnd32(__expf(SCALE_ * acc_s[mf][n][2*h+0]));
                    float p1 = rnd32(__expf(SCALE_ * acc_s[mf][n][2*h+1]));
                    rsum[mf][h] += p0 + p1;
                    const int ch0 = col >> 2;
                    const int sw  = (ch0 & ~7) | ((ch0 ^ row) & 7);
                    unsigned addr = psB + row*512 + sw*16 + (col & 3)*4;
                    asm volatile("st.shared.v2.f32 [%0], {%1,%2};"
                                 :: "r"(addr), "f"(p0), "f"(p1));
                }
        __syncthreads();

        // ================= PV phase =================
        float vreg[16];
        auto ldgV = [&](int vc) {
            const float* vp = Vp + (size_t)(kv0 + vc*32 + kbV)*QKV_N + nV;
            #pragma unroll
            for (int j = 0; j < 16; j++) vreg[j] = vp[(size_t)j*QKV_N];
        };
        auto stsV = [&](int buf) {
            #pragma unroll
            for (int qd = 0; qd < 4; qd++) {
                const int chv = (kbV >> 2) + qd;
                unsigned addr = vDst + buf*32768 + ((chv ^ (nV & 7))*16);
                asm volatile("st.shared.v4.f32 [%0], {%1,%2,%3,%4};"
                             :: "r"(addr),
                                "f"(vreg[qd*4+0]), "f"(vreg[qd*4+1]),
                                "f"(vreg[qd*4+2]), "f"(vreg[qd*4+3]));
            }
        };
        ldgV(0); stsV(0);
        __syncthreads();
        for (int vc = 0; vc < 4; vc++) {
            const int buf = vc & 1;
            const bool more = vc < 3;
            if (more) ldgV(vc + 1);
            const unsigned vB = vsB + buf*32768;
            #pragma unroll
            for (int k8 = 0; k8 < 4; k8++) {
                uint4 af, bf[4];
                {
                    const int kc = vc*8 + k8*2 + aHalf;
                    const int sw = (kc & ~7) | ((kc ^ aMp) & 7);
                    unsigned addr = psB + aMp*512 + (sw << 4);
                    asm volatile(
                        "ldmatrix.sync.aligned.m8n8.x4.shared.b16 {%0,%1,%2,%3}, [%4];"
                        : "=r"(af.x), "=r"(af.y), "=r"(af.z), "=r"(af.w)
                        : "r"(addr));
                }
                #pragma unroll
                for (int nf = 0; nf < 4; nf++) {
                    unsigned addr = vB + bNp[nf]*128
                                  + ((((k8<<1)+bHalf) ^ (bNp[nf]&7)) << 4);
                    asm volatile(
                        "ldmatrix.sync.aligned.m8n8.x4.shared.b16 {%0,%1,%2,%3}, [%4];"
                        : "=r"(bf[nf].x), "=r"(bf[nf].y), "=r"(bf[nf].z), "=r"(bf[nf].w)
                        : "r"(addr));
                }
                unsigned bp[8][2] = {
                    {bf[0].x, bf[0].y}, {bf[0].z, bf[0].w},
                    {bf[1].x, bf[1].y}, {bf[1].z, bf[1].w},
                    {bf[2].x, bf[2].y}, {bf[2].z, bf[2].w},
                    {bf[3].x, bf[3].y}, {bf[3].z, bf[3].w}};
                #pragma unroll
                for (int n8 = 0; n8 < 8; n8++)
                    asm volatile(
                        "mma.sync.aligned.m16n8k8.row.col.f32.tf32.tf32.f32 "
                        "{%0,%1,%2,%3}, {%4,%5,%6,%7}, {%8,%9}, {%0,%1,%2,%3};"
                        : "+f"(acc_o[n8][0]), "+f"(acc_o[n8][1]),
                          "+f"(acc_o[n8][2]), "+f"(acc_o[n8][3])
                        : "r"(af.x), "r"(af.y), "r"(af.z), "r"(af.w),
                          "r"(bp[n8][0]), "r"(bp[n8][1]));
            }
            if (more) {
                stsV(buf ^ 1);
                __syncthreads();
            }
        }
    }

    // ---- rowsum: warp reduce over t4, cross-warp via smem ----
    #pragma unroll
    for (int mf = 0; mf < 2; mf++)
        #pragma unroll
        for (int h = 0; h < 2; h++) {
            float s = rsum[mf][h];
            s += __shfl_xor_sync(0xffffffffu, s, 1);
            s += __shfl_xor_sync(0xffffffffu, s, 2);
            if (t4 == 0) redS[sc*64 + sr*32 + mf*16 + h*8 + g] = s;
        }
    __syncthreads();
    if (tid < 64) {
        float t = 0.f;
        #pragma unroll
        for (int c = 0; c < 8; c++) t += redS[c*64 + tid];
        rowTot[tid] = 1.0f / t;
    }
    __syncthreads();

    // ---- epilogue: normalize, round, store ----
    float* out = attn + (size_t)(bb*NN_ + q0)*INNER + hh*DD;
    #pragma unroll
    for (int n8 = 0; n8 < 8; n8++) {
        const int col = pc*64 + n8*8 + 2*t4;
        #pragma unroll
        for (int h = 0; h < 2; h++) {
            const int row = pr*16 + h*8 + g;
            const float inv = rowTot[row];
            float v0 = rnd32(acc_o[n8][2*h+0] * inv);
            float v1 = rnd32(acc_o[n8][2*h+1] * inv);
            *reinterpret_cast<float2*>(&out[(size_t)row*INNER + col]) =
                make_float2(v0, v1);
        }
    }
}

// ---------------- tf32 GEMM: cp.async A + ldmatrix (from R7) ---------------
// C = f(alpha * A[M,K] @ B[K,N]); row-major; A pre-rounded tf32.
// EPI: 1 round, 2 bias+gelu+round, 3 bias+residual(no round)
template<int EPI>
__global__ void __launch_bounds__(256)
gemm_tf32(const float* __restrict__ A, const float* __restrict__ B,
          const float* __restrict__ bias, const float* __restrict__ res,
          float* __restrict__ C,
          int K, int lda, int ldb, int ldc, float alpha)
{
    const int row0 = blockIdx.y * 128;
    const int col0 = blockIdx.x * 64;
    const int tid  = threadIdx.x;
    const int lane = tid & 31, wid = tid >> 5;
    const int wr = wid & 3, wc = wid >> 2;
    const int g  = lane >> 2, t4 = lane & 3;

    __shared__ unsigned As[2][128][32];
    __shared__ unsigned Bs[2][64][32];

    const unsigned asBase = (unsigned)__cvta_generic_to_shared(&As[0][0][0]);
    const unsigned bsBase = (unsigned)__cvta_generic_to_shared(&Bs[0][0][0]);

    const int rL  = tid >> 3;
    const int cL  = tid & 7;
    const int csw = (cL ^ (rL & 7)) * 16;

    const float* pA = A + (size_t)(row0 + rL)*lda + cL*4;
    unsigned aW[4];
    #pragma unroll
    for (int i = 0; i < 4; i++) aW[i] = asBase + (rL + 32*i)*128 + csw;

    const int nB  = tid & 63;
    const int kbB = (tid >> 6) * 8;
    float vbS[8];

    auto issue = [&](int kk, int buf) {
        #pragma unroll
        for (int i = 0; i < 4; i++) {
            const float* ga = pA + (size_t)i*32*lda + kk;
            asm volatile("cp.async.cg.shared.global [%0], [%1], 16;"
                         :: "r"(aW[i] + buf*16384), "l"(ga));
        }
        asm volatile("cp.async.commit_group;");
    };
    auto ldgB = [&](int kk) {
        #pragma unroll
        for (int w = 0; w < 8; w++)
            vbS[w] = B[(size_t)(kk + kbB + w)*ldb + col0 + nB];
    };
    auto stsB = [&](int buf) {
        const int c0 = kbB >> 2;
        uint4 u0 = make_uint4(f2tf32(vbS[0]), f2tf32(vbS[1]),
                              f2tf32(vbS[2]), f2tf32(vbS[3]));
        uint4 u1 = make_uint4(f2tf32(vbS[4]), f2tf32(vbS[5]),
                              f2tf32(vbS[6]), f2tf32(vbS[7]));
        *reinterpret_cast<uint4*>(&Bs[buf][nB][((c0  ) ^ (nB&7))*4]) = u0;
        *reinterpret_cast<uint4*>(&Bs[buf][nB][((c0+1) ^ (nB&7))*4]) = u1;
    };

    const int ami   = lane >> 3;
    const int aHalf = ami >> 1;
    const int aRoff = ((ami & 1) << 3) + (lane & 7);
    int aM[2], aSw[2];
    #pragma unroll
    for (int mf = 0; mf < 2; mf++) {
        aM[mf]  = wr*32 + mf*16 + aRoff;
        aSw[mf] = aM[mf] & 7;
    }
    const int bHalf = (lane >> 3) & 1;
    const int bRoff = ((lane >> 4) << 3) + (lane & 7);
    int bN[2], bSw[2];
    #pragma unroll
    for (int nf = 0; nf < 2; nf++) {
        bN[nf]  = wc*32 + nf*16 + bRoff;
        bSw[nf] = bN[nf] & 7;
    }

    float acc[2][4][4] = {};

    auto compute = [&](int buf) {
        const unsigned aBuf = asBase + buf*16384;
        const unsigned bBuf = bsBase + buf*8192;
        #pragma unroll
        for (int k8 = 0; k8 < 4; k8++) {
            uint4 af[2], bf[2];
            #pragma unroll
            for (int mf = 0; mf < 2; mf++) {
                unsigned addr = aBuf + aM[mf]*128
                              + ((((k8<<1) + aHalf) ^ aSw[mf]) << 4);
                asm volatile(
                    "ldmatrix.sync.aligned.m8n8.x4.shared.b16 {%0,%1,%2,%3}, [%4];"
                    : "=r"(af[mf].x), "=r"(af[mf].y), "=r"(af[mf].z), "=r"(af[mf].w)
                    : "r"(addr));
            }
            #pragma unroll
            for (int nf = 0; nf < 2; nf++) {
                unsigned addr = bBuf + bN[nf]*128
                              + ((((k8<<1) + bHalf) ^ bSw[nf]) << 4);
                asm volatile(
                    "ldmatrix.sync.aligned.m8n8.x4.shared.b16 {%0,%1,%2,%3}, [%4];"
                    : "=r"(bf[nf].x), "=r"(bf[nf].y), "=r"(bf[nf].z), "=r"(bf[nf].w)
                    : "r"(addr));
            }
            unsigned bp[4][2] = {
                {bf[0].x, bf[0].y}, {bf[0].z, bf[0].w},
                {bf[1].x, bf[1].y}, {bf[1].z, bf[1].w}};
            #pragma unroll
            for (int m = 0; m < 2; m++)
                #pragma unroll
                for (int n = 0; n < 4; n++)
                    asm volatile(
                        "mma.sync.aligned.m16n8k8.row.col.f32.tf32.tf32.f32 "
                        "{%0,%1,%2,%3}, {%4,%5,%6,%7}, {%8,%9}, {%0,%1,%2,%3};"
                        : "+f"(acc[m][n][0]), "+f"(acc[m][n][1]),
                          "+f"(acc[m][n][2]), "+f"(acc[m][n][3])
                        : "r"(af[m].x), "r"(af[m].y), "r"(af[m].z), "r"(af[m].w),
                          "r"(bp[n][0]), "r"(bp[n][1]));
        }
    };

    const int nch = K >> 5;
    issue(0, 0);
    ldgB(0);
    asm volatile("cp.async.wait_group 0;");
    stsB(0);
    __syncthreads();
    for (int ch = 0; ch < nch; ch++) {
        const int buf = ch & 1;
        const bool more = (ch + 1 < nch);
        if (more) { issue((ch + 1)*32, buf ^ 1); ldgB((ch + 1)*32); }
        compute(buf);
        if (more) {
            stsB(buf ^ 1);
            asm volatile("cp.async.wait_group 0;");
            __syncthreads();
        }
    }

    #pragma unroll
    for (int m = 0; m < 2; m++) {
        const int rbase = row0 + wr*32 + m*16 + g;
        #pragma unroll
        for (int n = 0; n < 4; n++) {
            const int c = col0 + wc*32 + n*8 + 2*t4;
            #pragma unroll
            for (int h = 0; h < 2; h++) {
                const int r = rbase + h*8;
                float v0 = acc[m][n][2*h+0] * alpha;
                float v1 = acc[m][n][2*h+1] * alpha;
                if (EPI >= 2) { v0 += bias[c]; v1 += bias[c+1]; }
                if (EPI == 2) {
                    v0 = 0.5f * v0 * (1.0f + erff(v0 * 0.70710678118654752f));
                    v1 = 0.5f * v1 * (1.0f + erff(v1 * 0.70710678118654752f));
                }
                if (EPI == 3) {
                    v0 += res[(size_t)r*ldc + c];
                    v1 += res[(size_t)r*ldc + c + 1];
                }
                if (EPI != 3) { v0 = rnd32(v0); v1 = rnd32(v1); }
                *reinterpret_cast<float2*>(&C[(size_t)r*ldc + c]) =
                    make_float2(v0, v1);
            }
        }
    }
}

// ---------------- host launcher ----------------
extern "C" void kernel_launch(void* const* d_in, const int* in_sizes, int n_in,
                              void* d_out, int out_size) {
    const float* inputs = (const float*)d_in[0];
    const float* ln1_g  = (const float*)d_in[1];
    const float* ln1_b  = (const float*)d_in[2];
    const float* w_qkv  = (const float*)d_in[3];
    const float* w_proj = (const float*)d_in[4];
    const float* b_proj = (const float*)d_in[5];
    const float* ln2_g  = (const float*)d_in[6];
    const float* ln2_b  = (const float*)d_in[7];
    const float* w1     = (const float*)d_in[8];
    const float* b1     = (const float*)d_in[9];
    const float* w2     = (const float*)d_in[10];
    const float* b2     = (const float*)d_in[11];
    float* x = (float*)d_out;

    float *ph, *pqkv, *pattn, *pmlp;
    cudaGetSymbolAddress((void**)&ph,    g_h);
    cudaGetSymbolAddress((void**)&pqkv,  g_qkv);
    cudaGetSymbolAddress((void**)&pattn, g_attn);
    cudaGetSymbolAddress((void**)&pmlp,  g_mlp);

    cudaFuncSetAttribute(flash_attn,
        cudaFuncAttributeMaxDynamicSharedMemorySize, FL_SMEM);

    cudaMemcpyAsync(x, inputs, (size_t)ROWS*DD*sizeof(float),
                    cudaMemcpyDeviceToDevice);

    const dim3 blk(256);

    for (int l = 0; l < LNUM; l++) {
        ln_kernel<<<ROWS/8, blk>>>(x, ln1_g + l*DD, ln1_b + l*DD, ph);

        // qkv = round(h @ w_qkv[l])
        gemm_tf32<1><<<dim3(QKV_N/64, ROWS/128, 1), blk>>>(
            ph, w_qkv + (size_t)l*DD*QKV_N, nullptr, nullptr,
            pqkv, DD, DD, QKV_N, QKV_N, 1.0f);

        // fused attention: scores+softmax+PV
        flash_attn<<<dim3(1, 16, 64), 512, FL_SMEM>>>(pqkv, pattn);

        // x = x + attn @ w_proj[l] + b_proj[l]
        gemm_tf32<3><<<dim3(DD/64, ROWS/128, 1), blk>>>(
            pattn, w_proj + (size_t)l*INNER*DD, b_proj + l*DD, x,
            x, INNER, INNER, DD, DD, 1.0f);

        ln_kernel<<<ROWS/8, blk>>>(x, ln2_g + l*DD, ln2_b + l*DD, ph);

        // hidden = round(gelu(h @ w1[l] + b1[l]))
        gemm_tf32<2><<<dim3(MM/64, ROWS/128, 1), blk>>>(
            ph, w1 + (size_t)l*DD*MM, b1 + l*MM, nullptr,
            pmlp, DD, DD, MM, MM, 1.0f);

        // x = x + hidden @ w2[l] + b2[l]
        gemm_tf32<3><<<dim3(DD/64, ROWS/128, 1), blk>>>(
            pmlp, w2 + (size_t)l*MM*DD, b2 + l*DD, x,
            x, MM, MM, DD, DD, 1.0f);
    }
}

// round 10
// speedup vs baseline: 1.4092x; 1.4092x over previous
#include <cuda_runtime.h>
#include <cuda_bf16.h>
#include <math.h>

// Problem constants
#define LNUM 4
#define DD   256
#define HH   8
#define INNER 2048
#define MM   1024
#define BB   8
#define NN_  1024
#define ROWS (BB*NN_)       // 8192
#define QKV_N (3*INNER)     // 6144
#define SCALE_ 0.0625f

// ---------------- device scratch ----------------
__device__ float g_h[(size_t)ROWS*DD];
__device__ float g_qkv[(size_t)ROWS*QKV_N];
__device__ float g_scores[(size_t)64*1024*1024];
__device__ float g_attn[(size_t)ROWS*INNER];
__device__ float g_mlp[(size_t)ROWS*MM];
__device__ float g_spart[(size_t)64*1024*16];   // per-row partial exp sums
__device__ float g_wqkvT[(size_t)LNUM*QKV_N*DD];
__device__ float g_wprojT[(size_t)LNUM*DD*INNER];
__device__ float g_w1T[(size_t)LNUM*MM*DD];
__device__ float g_w2T[(size_t)LNUM*DD*MM];

__device__ __forceinline__ unsigned f2tf32(float x) {
    unsigned r;
    asm("cvt.rna.tf32.f32 %0, %1;" : "=r"(r) : "f"(x));
    return r;
}
__device__ __forceinline__ float rnd32(float x) {
    return __uint_as_float(f2tf32(x));
}

// ---------------- LayerNorm: warp per row, outputs tf32-rounded ------------
__global__ void ln_kernel(const float* __restrict__ x,
                          const float* __restrict__ g,
                          const float* __restrict__ b,
                          float* __restrict__ out) {
    const int row  = blockIdx.x*8 + (threadIdx.x >> 5);
    const int lane = threadIdx.x & 31;
    const float* px = x + (size_t)row*DD;
    float4 a = *reinterpret_cast<const float4*>(px + lane*4);
    float4 c = *reinterpret_cast<const float4*>(px + 128 + lane*4);
    float s1 = a.x+a.y+a.z+a.w + c.x+c.y+c.z+c.w;
    float s2 = a.x*a.x+a.y*a.y+a.z*a.z+a.w*a.w
             + c.x*c.x+c.y*c.y+c.z*c.z+c.w*c.w;
    #pragma unroll
    for (int o = 16; o > 0; o >>= 1) {
        s1 += __shfl_xor_sync(0xffffffffu, s1, o);
        s2 += __shfl_xor_sync(0xffffffffu, s2, o);
    }
    const float mu = s1 * (1.0f/DD);
    const float rs = rsqrtf(s2 * (1.0f/DD) - mu*mu + 1e-5f);
    float4 g0 = *reinterpret_cast<const float4*>(g + lane*4);
    float4 g1 = *reinterpret_cast<const float4*>(g + 128 + lane*4);
    float4 b0 = *reinterpret_cast<const float4*>(b + lane*4);
    float4 b1 = *reinterpret_cast<const float4*>(b + 128 + lane*4);
    float* po = out + (size_t)row*DD;
    *reinterpret_cast<float4*>(po + lane*4) = make_float4(
        rnd32((a.x-mu)*rs*g0.x + b0.x), rnd32((a.y-mu)*rs*g0.y + b0.y),
        rnd32((a.z-mu)*rs*g0.z + b0.z), rnd32((a.w-mu)*rs*g0.w + b0.w));
    *reinterpret_cast<float4*>(po + 128 + lane*4) = make_float4(
        rnd32((c.x-mu)*rs*g1.x + b1.x), rnd32((c.y-mu)*rs*g1.y + b1.y),
        rnd32((c.z-mu)*rs*g1.z + b1.z), rnd32((c.w-mu)*rs*g1.w + b1.w));
}

// ---------------- transpose (+tf32 round): per z, src[R][C] -> dst[C][R] ---
__global__ void transpose_rnd(const float* __restrict__ src, float* __restrict__ dst,
                              int ldS, int ldD,
                              long long sSh, long long sDh) {
    __shared__ float tile[32][33];
    const int z = blockIdx.z;
    src += (size_t)z*sSh;
    dst += (size_t)z*sDh;
    const int c0 = blockIdx.x*32, r0 = blockIdx.y*32;
    const int tx = threadIdx.x, ty = threadIdx.y;
    #pragma unroll
    for (int i = ty; i < 32; i += 8)
        tile[i][tx] = src[(size_t)(r0+i)*ldS + c0 + tx];
    __syncthreads();
    #pragma unroll
    for (int i = ty; i < 32; i += 8)
        dst[(size_t)(c0+i)*ldD + r0 + tx] = rnd32(tile[tx][i]);
}

// ---------------- tf32 GEMM: cp.async A (+B if TB) + ldmatrix --------------
// C = f(alpha * A[M,K] @ op(B)); row-major.
// TB=false: B is [K,N] (reg-staged, tf32-rounded here).
// TB=true:  B is [N,K] (cp.async; must be pre-rounded, like A).
// A must always be pre-rounded tf32 in memory.
// Block 128x64, 8 warps (4r x 2c), warp 32x32, K-chunk 32, double-buffered.
// EPI: 1 round, 2 bias+gelu+round, 3 bias+residual(no round),
//      4 rowsum-normalize+round [reads auxR], 5 exp+round [writes auxW]
template<int EPI, bool TB>
__global__ void __launch_bounds__(256)
gemm_tf32(const float* __restrict__ A, const float* __restrict__ B,
          const float* __restrict__ bias, const float* __restrict__ res,
          const float* __restrict__ auxR, float* __restrict__ auxW,
          float* __restrict__ C,
          int K, int lda, int ldb, int ldc,
          long long sAb, long long sAh, long long sBb, long long sBh,
          long long sCb, long long sCh, float alpha)
{
    const int bb = blockIdx.z >> 3;
    const int hh = blockIdx.z & 7;
    A += (size_t)bb*sAb + (size_t)hh*sAh;
    B += (size_t)bb*sBb + (size_t)hh*sBh;
    C += (size_t)bb*sCb + (size_t)hh*sCh;

    const int row0 = blockIdx.y * 128;
    const int col0 = blockIdx.x * 64;
    const int tid  = threadIdx.x;
    const int lane = tid & 31, wid = tid >> 5;
    const int wr = wid & 3, wc = wid >> 2;
    const int g  = lane >> 2, t4 = lane & 3;

    __shared__ unsigned As[2][128][32];   // 32 KB
    __shared__ unsigned Bs[2][64][32];    // 16 KB
    __shared__ float redS[2][128];

    const unsigned asBase = (unsigned)__cvta_generic_to_shared(&As[0][0][0]);
    const unsigned bsBase = (unsigned)__cvta_generic_to_shared(&Bs[0][0][0]);

    // ---- async loader geometry (16B chunks)
    const int rL  = tid >> 3;           // 0..31
    const int cL  = tid & 7;            // chunk 0..7
    const int csw = (cL ^ (rL & 7)) * 16;

    const float* pA = A + (size_t)(row0 + rL)*lda + cL*4;
    const float* pB = B + (size_t)(col0 + rL)*ldb + cL*4;   // TB only
    unsigned aW[4], bWT[2];
    #pragma unroll
    for (int i = 0; i < 4; i++) aW[i] = asBase + (rL + 32*i)*128 + csw;
    #pragma unroll
    for (int i = 0; i < 2; i++) bWT[i] = bsBase + (rL + 32*i)*128 + csw;

    // ---- NN B loader (register staged, transposes + rounds)
    const int nB  = tid & 63;
    const int kbB = (tid >> 6) * 8;
    float vbS[8];

    auto issue = [&](int kk, int buf) {
        #pragma unroll
        for (int i = 0; i < 4; i++) {
            const float* ga = pA + (size_t)i*32*lda + kk;
            asm volatile("cp.async.cg.shared.global [%0], [%1], 16;"
                         :: "r"(aW[i] + buf*16384), "l"(ga));
        }
        if (TB) {
            #pragma unroll
            for (int i = 0; i < 2; i++) {
                const float* gb = pB + (size_t)i*32*ldb + kk;
                asm volatile("cp.async.cg.shared.global [%0], [%1], 16;"
                             :: "r"(bWT[i] + buf*8192), "l"(gb));
            }
        }
        asm volatile("cp.async.commit_group;");
    };
    auto ldgB = [&](int kk) {
        if (!TB) {
            #pragma unroll
            for (int w = 0; w < 8; w++)
                vbS[w] = B[(size_t)(kk + kbB + w)*ldb + col0 + nB];
        }
    };
    auto stsB = [&](int buf) {
        if (!TB) {
            const int c0 = kbB >> 2;
            uint4 u0 = make_uint4(f2tf32(vbS[0]), f2tf32(vbS[1]),
                                  f2tf32(vbS[2]), f2tf32(vbS[3]));
            uint4 u1 = make_uint4(f2tf32(vbS[4]), f2tf32(vbS[5]),
                                  f2tf32(vbS[6]), f2tf32(vbS[7]));
            *reinterpret_cast<uint4*>(&Bs[buf][nB][((c0  ) ^ (nB&7))*4]) = u0;
            *reinterpret_cast<uint4*>(&Bs[buf][nB][((c0+1) ^ (nB&7))*4]) = u1;
        }
    };

    // ---- ldmatrix address precompute
    const int ami   = lane >> 3;
    const int aHalf = ami >> 1;
    const int aRoff = ((ami & 1) << 3) + (lane & 7);
    int aM[2], aSw[2];
    #pragma unroll
    for (int mf = 0; mf < 2; mf++) {
        aM[mf]  = wr*32 + mf*16 + aRoff;
        aSw[mf] = aM[mf] & 7;
    }
    const int bHalf = (lane >> 3) & 1;
    const int bRoff = ((lane >> 4) << 3) + (lane & 7);
    int bN[2], bSw[2];
    #pragma unroll
    for (int nf = 0; nf < 2; nf++) {
        bN[nf]  = wc*32 + nf*16 + bRoff;
        bSw[nf] = bN[nf] & 7;
    }

    float acc[2][4][4] = {};

    auto compute = [&](int buf) {
        const unsigned aBuf = asBase + buf*16384;
        const unsigned bBuf = bsBase + buf*8192;
        #pragma unroll
        for (int k8 = 0; k8 < 4; k8++) {
            uint4 af[2], bf[2];
            #pragma unroll
            for (int mf = 0; mf < 2; mf++) {
                unsigned addr = aBuf + aM[mf]*128
                              + ((((k8<<1) + aHalf) ^ aSw[mf]) << 4);
                asm volatile(
                    "ldmatrix.sync.aligned.m8n8.x4.shared.b16 {%0,%1,%2,%3}, [%4];"
                    : "=r"(af[mf].x), "=r"(af[mf].y), "=r"(af[mf].z), "=r"(af[mf].w)
                    : "r"(addr));
            }
            #pragma unroll
            for (int nf = 0; nf < 2; nf++) {
                unsigned addr = bBuf + bN[nf]*128
                              + ((((k8<<1) + bHalf) ^ bSw[nf]) << 4);
                asm volatile(
                    "ldmatrix.sync.aligned.m8n8.x4.shared.b16 {%0,%1,%2,%3}, [%4];"
                    : "=r"(bf[nf].x), "=r"(bf[nf].y), "=r"(bf[nf].z), "=r"(bf[nf].w)
                    : "r"(addr));
            }
            unsigned bp[4][2] = {
                {bf[0].x, bf[0].y}, {bf[0].z, bf[0].w},
                {bf[1].x, bf[1].y}, {bf[1].z, bf[1].w}};
            #pragma unroll
            for (int m = 0; m < 2; m++)
                #pragma unroll
                for (int n = 0; n < 4; n++)
                    asm volatile(
                        "mma.sync.aligned.m16n8k8.row.col.f32.tf32.tf32.f32 "
                        "{%0,%1,%2,%3}, {%4,%5,%6,%7}, {%8,%9}, {%0,%1,%2,%3};"
                        : "+f"(acc[m][n][0]), "+f"(acc[m][n][1]),
                          "+f"(acc[m][n][2]), "+f"(acc[m][n][3])
                        : "r"(af[m].x), "r"(af[m].y), "r"(af[m].z), "r"(af[m].w),
                          "r"(bp[n][0]), "r"(bp[n][1]));
        }
    };

    const int nch = K >> 5;
    // prologue
    issue(0, 0);
    ldgB(0);
    asm volatile("cp.async.wait_group 0;");
    stsB(0);
    __syncthreads();
    // steady state: 1 barrier per chunk, cp.async overlaps compute
    for (int ch = 0; ch < nch; ch++) {
        const int buf = ch & 1;
        const bool more = (ch + 1 < nch);
        if (more) { issue((ch + 1)*32, buf ^ 1); ldgB((ch + 1)*32); }
        compute(buf);
        if (more) {
            stsB(buf ^ 1);
            asm volatile("cp.async.wait_group 0;");
            __syncthreads();
        }
    }

    // EPI4: gather per-row normalizers from partials
    if (EPI == 4) {
        if (tid < 128) {
            const float* p = auxR + ((size_t)blockIdx.z*1024 + row0 + tid)*16;
            float4 q0 = *reinterpret_cast<const float4*>(p);
            float4 q1 = *reinterpret_cast<const float4*>(p+4);
            float4 q2 = *reinterpret_cast<const float4*>(p+8);
            float4 q3 = *reinterpret_cast<const float4*>(p+12);
            redS[0][tid] = (q0.x+q0.y+q0.z+q0.w) + (q1.x+q1.y+q1.z+q1.w)
                         + (q2.x+q2.y+q2.z+q2.w) + (q3.x+q3.y+q3.z+q3.w);
        }
        __syncthreads();
    }

    float rsums[2][2] = {};

    // epilogue
    #pragma unroll
    for (int m = 0; m < 2; m++) {
        const int rb = wr*32 + m*16 + g;
        #pragma unroll
        for (int n = 0; n < 4; n++) {
            const int c = col0 + wc*32 + n*8 + 2*t4;
            #pragma unroll
            for (int h = 0; h < 2; h++) {
                const int rl = rb + h*8;
                const int r  = row0 + rl;
                float v0 = acc[m][n][2*h+0] * alpha;
                float v1 = acc[m][n][2*h+1] * alpha;
                if (EPI == 2 || EPI == 3) { v0 += bias[c]; v1 += bias[c+1]; }
                if (EPI == 2) {
                    v0 = 0.5f * v0 * (1.0f + erff(v0 * 0.70710678118654752f));
                    v1 = 0.5f * v1 * (1.0f + erff(v1 * 0.70710678118654752f));
                }
                if (EPI == 3) {
                    v0 += res[(size_t)r*ldc + c];
                    v1 += res[(size_t)r*ldc + c + 1];
                }
                if (EPI == 4) {
                    const float inv = 1.0f / redS[0][rl];
                    v0 *= inv; v1 *= inv;
                }
                if (EPI == 5) { v0 = __expf(v0); v1 = __expf(v1); }
                if (EPI != 3) { v0 = rnd32(v0); v1 = rnd32(v1); }
                if (EPI == 5) rsums[m][h] += v0 + v1;
                *reinterpret_cast<float2*>(&C[(size_t)r*ldc + c]) =
                    make_float2(v0, v1);
            }
        }
    }

    // EPI5: deterministic per-row partial sums
    if (EPI == 5) {
        #pragma unroll
        for (int m = 0; m < 2; m++)
            #pragma unroll
            for (int h = 0; h < 2; h++) {
                float s = rsums[m][h];
                s += __shfl_xor_sync(0xffffffffu, s, 1);
                s += __shfl_xor_sync(0xffffffffu, s, 2);
                if (t4 == 0) redS[wc][wr*32 + m*16 + h*8 + g] = s;
            }
        __syncthreads();
        if (tid < 128) {
            float tot = redS[0][tid] + redS[1][tid];
            auxW[((size_t)blockIdx.z*1024 + row0 + tid)*16 + blockIdx.x] = tot;
        }
    }
}

// ---------------- host launcher ----------------
extern "C" void kernel_launch(void* const* d_in, const int* in_sizes, int n_in,
                              void* d_out, int out_size) {
    const float* inputs = (const float*)d_in[0];
    const float* ln1_g  = (const float*)d_in[1];
    const float* ln1_b  = (const float*)d_in[2];
    const float* w_qkv  = (const float*)d_in[3];
    const float* w_proj = (const float*)d_in[4];
    const float* b_proj = (const float*)d_in[5];
    const float* ln2_g  = (const float*)d_in[6];
    const float* ln2_b  = (const float*)d_in[7];
    const float* w1     = (const float*)d_in[8];
    const float* b1     = (const float*)d_in[9];
    const float* w2     = (const float*)d_in[10];
    const float* b2     = (const float*)d_in[11];
    float* x = (float*)d_out;

    float *ph, *pqkv, *pscores, *pattn, *pmlp, *pspart;
    float *pwqkvT, *pwprojT, *pw1T, *pw2T;
    cudaGetSymbolAddress((void**)&ph,      g_h);
    cudaGetSymbolAddress((void**)&pqkv,    g_qkv);
    cudaGetSymbolAddress((void**)&pscores, g_scores);
    cudaGetSymbolAddress((void**)&pattn,   g_attn);
    cudaGetSymbolAddress((void**)&pmlp,    g_mlp);
    cudaGetSymbolAddress((void**)&pspart,  g_spart);
    cudaGetSymbolAddress((void**)&pwqkvT,  g_wqkvT);
    cudaGetSymbolAddress((void**)&pwprojT, g_wprojT);
    cudaGetSymbolAddress((void**)&pw1T,    g_w1T);
    cudaGetSymbolAddress((void**)&pw2T,    g_w2T);

    cudaMemcpyAsync(x, inputs, (size_t)ROWS*DD*sizeof(float),
                    cudaMemcpyDeviceToDevice);

    const dim3 blk(256);
    const dim3 tblk(32, 8);

    // ---- one-time weight transposes (+tf32 rounding); z = layer
    transpose_rnd<<<dim3(QKV_N/32, DD/32, LNUM), tblk>>>(
        w_qkv, pwqkvT, QKV_N, DD,
        (long long)DD*QKV_N, (long long)QKV_N*DD);
    transpose_rnd<<<dim3(DD/32, INNER/32, LNUM), tblk>>>(
        w_proj, pwprojT, DD, INNER,
        (long long)INNER*DD, (long long)DD*INNER);
    transpose_rnd<<<dim3(MM/32, DD/32, LNUM), tblk>>>(
        w1, pw1T, MM, DD,
        (long long)DD*MM, (long long)MM*DD);
    transpose_rnd<<<dim3(DD/32, MM/32, LNUM), tblk>>>(
        w2, pw2T, DD, MM,
        (long long)MM*DD, (long long)DD*MM);

    for (int l = 0; l < LNUM; l++) {
        ln_kernel<<<ROWS/8, blk>>>(x, ln1_g + l*DD, ln1_b + l*DD, ph);

        // qkv = round(h @ w_qkvT^T)      [TB: both operands cp.async]
        gemm_tf32<1,true><<<dim3(QKV_N/64, ROWS/128, 1), blk>>>(
            ph, pwqkvT + (size_t)l*QKV_N*DD, nullptr, nullptr, nullptr, nullptr,
            pqkv, DD, DD, DD, QKV_N,
            0,0,0,0,0,0, 1.0f);

        // scoresExp = round(exp(SCALE * Q @ K^T)) + partial rowsums
        gemm_tf32<5,true><<<dim3(1024/64, 1024/128, 64), blk>>>(
            pqkv, pqkv + INNER, nullptr, nullptr, nullptr, pspart,
            pscores, DD, QKV_N, QKV_N, 1024,
            (long long)NN_*QKV_N, DD,
            (long long)NN_*QKV_N, DD,
            8LL*1024*1024, 1024LL*1024,
            SCALE_);

        // attn = round((scoresExp @ V) / rowsum)   [NN: V reg-staged]
        gemm_tf32<4,false><<<dim3(DD/64, 1024/128, 64), blk>>>(
            pscores, pqkv + 2*INNER, nullptr, nullptr, pspart, nullptr,
            pattn, 1024, 1024, QKV_N, INNER,
            8LL*1024*1024, 1024LL*1024,
            (long long)NN_*QKV_N, DD,
            (long long)NN_*INNER, DD,
            1.0f);

        // x = x + attn @ w_projT^T + b_proj
        gemm_tf32<3,true><<<dim3(DD/64, ROWS/128, 1), blk>>>(
            pattn, pwprojT + (size_t)l*DD*INNER, b_proj + l*DD, x, nullptr, nullptr,
            x, INNER, INNER, INNER, DD,
            0,0,0,0,0,0, 1.0f);

        ln_kernel<<<ROWS/8, blk>>>(x, ln2_g + l*DD, ln2_b + l*DD, ph);

        // hidden = round(gelu(h @ w1T^T + b1))
        gemm_tf32<2,true><<<dim3(MM/64, ROWS/128, 1), blk>>>(
            ph, pw1T + (size_t)l*MM*DD, b1 + l*MM, nullptr, nullptr, nullptr,
            pmlp, DD, DD, DD, MM,
            0,0,0,0,0,0, 1.0f);

        // x = x + hidden @ w2T^T + b2
        gemm_tf32<3,true><<<dim3(DD/64, ROWS/128, 1), blk>>>(
            pmlp, pw2T + (size_t)l*DD*MM, b2 + l*DD, x, nullptr, nullptr,
            x, MM, MM, MM, DD,
            0,0,0,0,0,0, 1.0f);
    }
}

// round 12
// speedup vs baseline: 1.4378x; 1.0203x over previous
#include <cuda_runtime.h>
#include <cuda_bf16.h>
#include <math.h>

// Problem constants
#define LNUM 4
#define DD   256
#define HH   8
#define INNER 2048
#define MM   1024
#define BB   8
#define NN_  1024
#define ROWS (BB*NN_)       // 8192
#define QKV_N (3*INNER)     // 6144
#define SCALE_ 0.0625f

// ---------------- device scratch ----------------
__device__ float g_h[(size_t)ROWS*DD];
__device__ float g_qkv[(size_t)ROWS*QKV_N];
__device__ float g_scores[(size_t)64*1024*1024];
__device__ float g_attn[(size_t)ROWS*INNER];
__device__ float g_mlp[(size_t)ROWS*MM];
__device__ float g_spart[(size_t)64*1024*16];   // per-row partial exp sums
__device__ float g_wqkvT[(size_t)LNUM*QKV_N*DD];
__device__ float g_wprojT[(size_t)LNUM*DD*INNER];
__device__ float g_w1T[(size_t)LNUM*MM*DD];
__device__ float g_w2T[(size_t)LNUM*DD*MM];

__device__ __forceinline__ unsigned f2tf32(float x) {
    unsigned r;
    asm("cvt.rna.tf32.f32 %0, %1;" : "=r"(r) : "f"(x));
    return r;
}
__device__ __forceinline__ float rnd32(float x) {
    return __uint_as_float(f2tf32(x));
}

// ---------------- LayerNorm: warp per row, outputs tf32-rounded ------------
__global__ void ln_kernel(const float* __restrict__ x,
                          const float* __restrict__ g,
                          const float* __restrict__ b,
                          float* __restrict__ out) {
    const int row  = blockIdx.x*8 + (threadIdx.x >> 5);
    const int lane = threadIdx.x & 31;
    const float* px = x + (size_t)row*DD;
    float4 a = *reinterpret_cast<const float4*>(px + lane*4);
    float4 c = *reinterpret_cast<const float4*>(px + 128 + lane*4);
    float s1 = a.x+a.y+a.z+a.w + c.x+c.y+c.z+c.w;
    float s2 = a.x*a.x+a.y*a.y+a.z*a.z+a.w*a.w
             + c.x*c.x+c.y*c.y+c.z*c.z+c.w*c.w;
    #pragma unroll
    for (int o = 16; o > 0; o >>= 1) {
        s1 += __shfl_xor_sync(0xffffffffu, s1, o);
        s2 += __shfl_xor_sync(0xffffffffu, s2, o);
    }
    const float mu = s1 * (1.0f/DD);
    const float rs = rsqrtf(s2 * (1.0f/DD) - mu*mu + 1e-5f);
    float4 g0 = *reinterpret_cast<const float4*>(g + lane*4);
    float4 g1 = *reinterpret_cast<const float4*>(g + 128 + lane*4);
    float4 b0 = *reinterpret_cast<const float4*>(b + lane*4);
    float4 b1 = *reinterpret_cast<const float4*>(b + 128 + lane*4);
    float* po = out + (size_t)row*DD;
    *reinterpret_cast<float4*>(po + lane*4) = make_float4(
        rnd32((a.x-mu)*rs*g0.x + b0.x), rnd32((a.y-mu)*rs*g0.y + b0.y),
        rnd32((a.z-mu)*rs*g0.z + b0.z), rnd32((a.w-mu)*rs*g0.w + b0.w));
    *reinterpret_cast<float4*>(po + 128 + lane*4) = make_float4(
        rnd32((c.x-mu)*rs*g1.x + b1.x), rnd32((c.y-mu)*rs*g1.y + b1.y),
        rnd32((c.z-mu)*rs*g1.z + b1.z), rnd32((c.w-mu)*rs*g1.w + b1.w));
}

// ---------------- transpose (+tf32 round): per z, src[R][C] -> dst[C][R] ---
__global__ void transpose_rnd(const float* __restrict__ src, float* __restrict__ dst,
                              int ldS, int ldD,
                              long long sSh, long long sDh) {
    __shared__ float tile[32][33];
    const int z = blockIdx.z;
    src += (size_t)z*sSh;
    dst += (size_t)z*sDh;
    const int c0 = blockIdx.x*32, r0 = blockIdx.y*32;
    const int tx = threadIdx.x, ty = threadIdx.y;
    #pragma unroll
    for (int i = ty; i < 32; i += 8)
        tile[i][tx] = src[(size_t)(r0+i)*ldS + c0 + tx];
    __syncthreads();
    #pragma unroll
    for (int i = ty; i < 32; i += 8)
        dst[(size_t)(c0+i)*ldD + r0 + tx] = rnd32(tile[tx][i]);
}

// ---------------- tf32 GEMM: cp.async + ldmatrix, tile 128 x BN ------------
// C = f(alpha * A[M,K] @ op(B)); row-major; A (and B if TB) pre-rounded tf32.
// TB=false: B is [K,N] (reg-staged, rounded here; BN=64 only).
// TB=true:  B is [N,K] (cp.async).
// 8 warps (4r x 2c); warp tile 32 x (BN/2); K-chunk 32; double-buffered.
// Dynamic smem: As 2x(128x128B)=32768 @0, Bs 2x(BNx128B) @32768, redS after.
// EPI: 1 round, 2 bias+gelu+round, 3 bias+residual(no round),
//      4 rowsum-normalize+round [reads auxR, 8 partials], 5 exp+round [writes auxW]
template<int EPI, bool TB, int BN>
__global__ void __launch_bounds__(256)
gemm_tf32(const float* __restrict__ A, const float* __restrict__ B,
          const float* __restrict__ bias, const float* __restrict__ res,
          const float* __restrict__ auxR, float* __restrict__ auxW,
          float* __restrict__ C,
          int K, int lda, int ldb, int ldc,
          long long sAb, long long sAh, long long sBb, long long sBh,
          long long sCb, long long sCh, float alpha)
{
    constexpr int NF = BN / 32;          // b-frags (16-col) per warp
    constexpr int BUFB = BN * 128;       // bytes per B buffer
    constexpr int BUFA = 16384;          // bytes per A buffer (128 rows x 128B)

    const int bb = blockIdx.z >> 3;
    const int hh = blockIdx.z & 7;
    A += (size_t)bb*sAb + (size_t)hh*sAh;
    B += (size_t)bb*sBb + (size_t)hh*sBh;
    C += (size_t)bb*sCb + (size_t)hh*sCh;

    const int row0 = blockIdx.y * 128;
    const int col0 = blockIdx.x * BN;
    const int tid  = threadIdx.x;
    const int lane = tid & 31, wid = tid >> 5;
    const int wr = wid & 3, wc = wid >> 2;
    const int g  = lane >> 2, t4 = lane & 3;

    extern __shared__ char smraw[];
    const unsigned asBase = (unsigned)__cvta_generic_to_shared(smraw);
    const unsigned bsBase = asBase + 2*BUFA;
    float* redS = (float*)(smraw + 2*BUFA + 2*BUFB);   // [2][128]

    // ---- async loader geometry (16B chunks)
    const int rL  = tid >> 3;           // 0..31
    const int cL  = tid & 7;            // chunk 0..7
    const int csw = (cL ^ (rL & 7)) * 16;

    const float* pA = A + (size_t)(row0 + rL)*lda + cL*4;
    const float* pB = B + (size_t)(col0 + rL)*ldb + cL*4;   // TB only
    unsigned aW[4], bWT[NF];
    #pragma unroll
    for (int i = 0; i < 4; i++) aW[i] = asBase + (rL + 32*i)*128 + csw;
    #pragma unroll
    for (int i = 0; i < NF; i++) bWT[i] = bsBase + (rL + 32*i)*128 + csw;

    // ---- NN B loader (register staged; BN==64 path)
    const int nB  = tid & 63;
    const int kbB = (tid >> 6) * 8;
    float vbS[8];

    auto issue = [&](int kk, int buf) {
        #pragma unroll
        for (int i = 0; i < 4; i++) {
            const float* ga = pA + (size_t)i*32*lda + kk;
            asm volatile("cp.async.cg.shared.global [%0], [%1], 16;"
                         :: "r"(aW[i] + buf*BUFA), "l"(ga));
        }
        if (TB) {
            #pragma unroll
            for (int i = 0; i < NF; i++) {
                const float* gb = pB + (size_t)i*32*ldb + kk;
                asm volatile("cp.async.cg.shared.global [%0], [%1], 16;"
                             :: "r"(bWT[i] + buf*BUFB), "l"(gb));
            }
        }
        asm volatile("cp.async.commit_group;");
    };
    auto ldgB = [&](int kk) {
        if (!TB) {
            #pragma unroll
            for (int w = 0; w < 8; w++)
                vbS[w] = B[(size_t)(kk + kbB + w)*ldb + col0 + nB];
        }
    };
    auto stsB = [&](int buf) {
        if (!TB) {
            const int c0 = kbB >> 2;
            uint4 u0 = make_uint4(f2tf32(vbS[0]), f2tf32(vbS[1]),
                                  f2tf32(vbS[2]), f2tf32(vbS[3]));
            uint4 u1 = make_uint4(f2tf32(vbS[4]), f2tf32(vbS[5]),
                                  f2tf32(vbS[6]), f2tf32(vbS[7]));
            char* base = smraw + 2*BUFA + buf*BUFB + nB*128;
            *reinterpret_cast<uint4*>(base + (((c0  ) ^ (nB&7))<<4)) = u0;
            *reinterpret_cast<uint4*>(base + (((c0+1) ^ (nB&7))<<4)) = u1;
        }
    };

    // ---- ldmatrix address precompute
    const int ami   = lane >> 3;
    const int aHalf = ami >> 1;
    const int aRoff = ((ami & 1) << 3) + (lane & 7);
    int aM[2], aSw[2];
    #pragma unroll
    for (int mf = 0; mf < 2; mf++) {
        aM[mf]  = wr*32 + mf*16 + aRoff;
        aSw[mf] = aM[mf] & 7;
    }
    const int bHalf = (lane >> 3) & 1;
    const int bRoff = ((lane >> 4) << 3) + (lane & 7);
    int bN[NF], bSw[NF];
    #pragma unroll
    for (int nf = 0; nf < NF; nf++) {
        bN[nf]  = wc*(BN/2) + nf*16 + bRoff;
        bSw[nf] = bN[nf] & 7;
    }

    float acc[2][2*NF][4] = {};

    auto compute = [&](int buf) {
        const unsigned aBuf = asBase + buf*BUFA;
        const unsigned bBuf = bsBase + buf*BUFB;
        #pragma unroll
        for (int k8 = 0; k8 < 4; k8++) {
            uint4 af[2], bf[NF];
            #pragma unroll
            for (int mf = 0; mf < 2; mf++) {
                unsigned addr = aBuf + aM[mf]*128
                              + ((((k8<<1) + aHalf) ^ aSw[mf]) << 4);
                asm volatile(
                    "ldmatrix.sync.aligned.m8n8.x4.shared.b16 {%0,%1,%2,%3}, [%4];"
                    : "=r"(af[mf].x), "=r"(af[mf].y), "=r"(af[mf].z), "=r"(af[mf].w)
                    : "r"(addr));
            }
            #pragma unroll
            for (int nf = 0; nf < NF; nf++) {
                unsigned addr = bBuf + bN[nf]*128
                              + ((((k8<<1) + bHalf) ^ bSw[nf]) << 4);
                asm volatile(
                    "ldmatrix.sync.aligned.m8n8.x4.shared.b16 {%0,%1,%2,%3}, [%4];"
                    : "=r"(bf[nf].x), "=r"(bf[nf].y), "=r"(bf[nf].z), "=r"(bf[nf].w)
                    : "r"(addr));
            }
            #pragma unroll
            for (int m = 0; m < 2; m++)
                #pragma unroll
                for (int n = 0; n < 2*NF; n++) {
                    const unsigned b0 = (n & 1) ? bf[n>>1].z : bf[n>>1].x;
                    const unsigned b1 = (n & 1) ? bf[n>>1].w : bf[n>>1].y;
                    asm volatile(
                        "mma.sync.aligned.m16n8k8.row.col.f32.tf32.tf32.f32 "
                        "{%0,%1,%2,%3}, {%4,%5,%6,%7}, {%8,%9}, {%0,%1,%2,%3};"
                        : "+f"(acc[m][n][0]), "+f"(acc[m][n][1]),
                          "+f"(acc[m][n][2]), "+f"(acc[m][n][3])
                        : "r"(af[m].x), "r"(af[m].y), "r"(af[m].z), "r"(af[m].w),
                          "r"(b0), "r"(b1));
                }
        }
    };

    const int nch = K >> 5;
    issue(0, 0);
    ldgB(0);
    asm volatile("cp.async.wait_group 0;");
    stsB(0);
    __syncthreads();
    for (int ch = 0; ch < nch; ch++) {
        const int buf = ch & 1;
        const bool more = (ch + 1 < nch);
        if (more) { issue((ch + 1)*32, buf ^ 1); ldgB((ch + 1)*32); }
        compute(buf);
        if (more) {
            stsB(buf ^ 1);
            asm volatile("cp.async.wait_group 0;");
            __syncthreads();
        }
    }

    // EPI4: gather per-row normalizers (8 partials per row)
    if (EPI == 4) {
        if (tid < 128) {
            const float* p = auxR + ((size_t)blockIdx.z*1024 + row0 + tid)*16;
            float4 q0 = *reinterpret_cast<const float4*>(p);
            float4 q1 = *reinterpret_cast<const float4*>(p+4);
            redS[tid] = (q0.x+q0.y+q0.z+q0.w) + (q1.x+q1.y+q1.z+q1.w);
        }
        __syncthreads();
    }

    float rsums[2][2] = {};

    // epilogue
    #pragma unroll
    for (int m = 0; m < 2; m++) {
        const int rb = wr*32 + m*16 + g;
        #pragma unroll
        for (int n = 0; n < 2*NF; n++) {
            const int c = col0 + wc*(BN/2) + n*8 + 2*t4;
            #pragma unroll
            for (int h = 0; h < 2; h++) {
                const int rl = rb + h*8;
                const int r  = row0 + rl;
                float v0 = acc[m][n][2*h+0] * alpha;
                float v1 = acc[m][n][2*h+1] * alpha;
                if (EPI == 2 || EPI == 3) { v0 += bias[c]; v1 += bias[c+1]; }
                if (EPI == 2) {
                    v0 = 0.5f * v0 * (1.0f + erff(v0 * 0.70710678118654752f));
                    v1 = 0.5f * v1 * (1.0f + erff(v1 * 0.70710678118654752f));
                }
                if (EPI == 3) {
                    v0 += res[(size_t)r*ldc + c];
                    v1 += res[(size_t)r*ldc + c + 1];
                }
                if (EPI == 4) {
                    const float inv = 1.0f / redS[rl];
                    v0 *= inv; v1 *= inv;
                }
                if (EPI == 5) { v0 = __expf(v0); v1 = __expf(v1); }
                if (EPI != 3) { v0 = rnd32(v0); v1 = rnd32(v1); }
                if (EPI == 5) rsums[m][h] += v0 + v1;
                *reinterpret_cast<float2*>(&C[(size_t)r*ldc + c]) =
                    make_float2(v0, v1);
            }
        }
    }

    // EPI5: deterministic per-row partial sums
    if (EPI == 5) {
        #pragma unroll
        for (int m = 0; m < 2; m++)
            #pragma unroll
            for (int h = 0; h < 2; h++) {
                float s = rsums[m][h];
                s += __shfl_xor_sync(0xffffffffu, s, 1);
                s += __shfl_xor_sync(0xffffffffu, s, 2);
                if (t4 == 0) redS[wc*128 + wr*32 + m*16 + h*8 + g] = s;
            }
        __syncthreads();
        if (tid < 128) {
            float tot = redS[tid] + redS[128 + tid];
            auxW[((size_t)blockIdx.z*1024 + row0 + tid)*16 + blockIdx.x] = tot;
        }
    }
}

// smem sizes per BN
#define SMEM_BN128 (32768 + 2*128*128 + 1024)   // 66560
#define SMEM_BN64  (32768 + 2*64*128 + 1024)    // 50176

// ---------------- host launcher ----------------
extern "C" void kernel_launch(void* const* d_in, const int* in_sizes, int n_in,
                              void* d_out, int out_size) {
    const float* inputs = (const float*)d_in[0];
    const float* ln1_g  = (const float*)d_in[1];
    const float* ln1_b  = (const float*)d_in[2];
    const float* w_qkv  = (const float*)d_in[3];
    const float* w_proj = (const float*)d_in[4];
    const float* b_proj = (const float*)d_in[5];
    const float* ln2_g  = (const float*)d_in[6];
    const float* ln2_b  = (const float*)d_in[7];
    const float* w1     = (const float*)d_in[8];
    const float* b1     = (const float*)d_in[9];
    const float* w2     = (const float*)d_in[10];
    const float* b2     = (const float*)d_in[11];
    float* x = (float*)d_out;

    float *ph, *pqkv, *pscores, *pattn, *pmlp, *pspart;
    float *pwqkvT, *pwprojT, *pw1T, *pw2T;
    cudaGetSymbolAddress((void**)&ph,      g_h);
    cudaGetSymbolAddress((void**)&pqkv,    g_qkv);
    cudaGetSymbolAddress((void**)&pscores, g_scores);
    cudaGetSymbolAddress((void**)&pattn,   g_attn);
    cudaGetSymbolAddress((void**)&pmlp,    g_mlp);
    cudaGetSymbolAddress((void**)&pspart,  g_spart);
    cudaGetSymbolAddress((void**)&pwqkvT,  g_wqkvT);
    cudaGetSymbolAddress((void**)&pwprojT, g_wprojT);
    cudaGetSymbolAddress((void**)&pw1T,    g_w1T);
    cudaGetSymbolAddress((void**)&pw2T,    g_w2T);

    // raise dynamic smem limits (host-side, safe pre-capture)
    cudaFuncSetAttribute(gemm_tf32<1,true,128>,
        cudaFuncAttributeMaxDynamicSharedMemorySize, SMEM_BN128);
    cudaFuncSetAttribute(gemm_tf32<5,true,128>,
        cudaFuncAttributeMaxDynamicSharedMemorySize, SMEM_BN128);
    cudaFuncSetAttribute(gemm_tf32<3,true,128>,
        cudaFuncAttributeMaxDynamicSharedMemorySize, SMEM_BN128);
    cudaFuncSetAttribute(gemm_tf32<2,true,128>,
        cudaFuncAttributeMaxDynamicSharedMemorySize, SMEM_BN128);
    cudaFuncSetAttribute(gemm_tf32<4,false,64>,
        cudaFuncAttributeMaxDynamicSharedMemorySize, SMEM_BN64);

    cudaMemcpyAsync(x, inputs, (size_t)ROWS*DD*sizeof(float),
                    cudaMemcpyDeviceToDevice);

    const dim3 blk(256);
    const dim3 tblk(32, 8);

    // ---- one-time weight transposes (+tf32 rounding); z = layer
    transpose_rnd<<<dim3(QKV_N/32, DD/32, LNUM), tblk>>>(
        w_qkv, pwqkvT, QKV_N, DD,
        (long long)DD*QKV_N, (long long)QKV_N*DD);
    transpose_rnd<<<dim3(DD/32, INNER/32, LNUM), tblk>>>(
        w_proj, pwprojT, DD, INNER,
        (long long)INNER*DD, (long long)DD*INNER);
    transpose_rnd<<<dim3(MM/32, DD/32, LNUM), tblk>>>(
        w1, pw1T, MM, DD,
        (long long)DD*MM, (long long)MM*DD);
    transpose_rnd<<<dim3(DD/32, MM/32, LNUM), tblk>>>(
        w2, pw2T, DD, MM,
        (long long)MM*DD, (long long)DD*MM);

    for (int l = 0; l < LNUM; l++) {
        ln_kernel<<<ROWS/8, blk>>>(x, ln1_g + l*DD, ln1_b + l*DD, ph);

        // qkv = round(h @ w_qkvT^T)
        gemm_tf32<1,true,128><<<dim3(QKV_N/128, ROWS/128, 1), blk, SMEM_BN128>>>(
            ph, pwqkvT + (size_t)l*QKV_N*DD, nullptr, nullptr, nullptr, nullptr,
            pqkv, DD, DD, DD, QKV_N,
            0,0,0,0,0,0, 1.0f);

        // scoresExp = round(exp(SCALE * Q @ K^T)) + 8 partial rowsums/row
        gemm_tf32<5,true,128><<<dim3(1024/128, 1024/128, 64), blk, SMEM_BN128>>>(
            pqkv, pqkv + INNER, nullptr, nullptr, nullptr, pspart,
            pscores, DD, QKV_N, QKV_N, 1024,
            (long long)NN_*QKV_N, DD,
            (long long)NN_*QKV_N, DD,
            8LL*1024*1024, 1024LL*1024,
            SCALE_);

        // attn = round((scoresExp @ V) / rowsum)   [NN: V reg-staged]
        gemm_tf32<4,false,64><<<dim3(DD/64, 1024/128, 64), blk, SMEM_BN64>>>(
            pscores, pqkv + 2*INNER, nullptr, nullptr, pspart, nullptr,
            pattn, 1024, 1024, QKV_N, INNER,
            8LL*1024*1024, 1024LL*1024,
            (long long)NN_*QKV_N, DD,
            (long long)NN_*INNER, DD,
            1.0f);

        // x = x + attn @ w_projT^T + b_proj
        gemm_tf32<3,true,128><<<dim3(DD/128, ROWS/128, 1), blk, SMEM_BN128>>>(
            pattn, pwprojT + (size_t)l*DD*INNER, b_proj + l*DD, x, nullptr, nullptr,
            x, INNER, INNER, INNER, DD,
            0,0,0,0,0,0, 1.0f);

        ln_kernel<<<ROWS/8, blk>>>(x, ln2_g + l*DD, ln2_b + l*DD, ph);

        // hidden = round(gelu(h @ w1T^T + b1))
        gemm_tf32<2,true,128><<<dim3(MM/128, ROWS/128, 1), blk, SMEM_BN128>>>(
            ph, pw1T + (size_t)l*MM*DD, b1 + l*MM, nullptr, nullptr, nullptr,
            pmlp, DD, DD, DD, MM,
            0,0,0,0,0,0, 1.0f);

        // x = x + hidden @ w2T^T + b2
        gemm_tf32<3,true,128><<<dim3(DD/128, ROWS/128, 1), blk, SMEM_BN128>>>(
            pmlp, pw2T + (size_t)l*DD*MM, b2 + l*DD, x, nullptr, nullptr,
            x, MM, MM, MM, DD,
            0,0,0,0,0,0, 1.0f);
    }
}

// round 13
// speedup vs baseline: 1.4455x; 1.0054x over previous
#include <cuda_runtime.h>
#include <cuda_bf16.h>
#include <math.h>

// Problem constants
#define LNUM 4
#define DD   256
#define HH   8
#define INNER 2048
#define MM   1024
#define BB   8
#define NN_  1024
#define ROWS (BB*NN_)       // 8192
#define QKV_N (3*INNER)     // 6144
#define SCALE_ 0.0625f

// ---------------- device scratch ----------------
__device__ float g_h[(size_t)ROWS*DD];
__device__ float g_qkv[(size_t)ROWS*QKV_N];
__device__ float g_scores[(size_t)64*1024*1024];
__device__ float g_attn[(size_t)ROWS*INNER];
__device__ float g_mlp[(size_t)ROWS*MM];
__device__ float g_spart[(size_t)64*1024*16];   // per-row partial exp sums
__device__ float g_vT[(size_t)64*DD*NN_];       // V^T per (b,h): [256][1024]
__device__ float g_wqkvT[(size_t)LNUM*QKV_N*DD];
__device__ float g_wprojT[(size_t)LNUM*DD*INNER];
__device__ float g_w1T[(size_t)LNUM*MM*DD];
__device__ float g_w2T[(size_t)LNUM*DD*MM];

__device__ __forceinline__ unsigned f2tf32(float x) {
    unsigned r;
    asm("cvt.rna.tf32.f32 %0, %1;" : "=r"(r) : "f"(x));
    return r;
}
__device__ __forceinline__ float rnd32(float x) {
    return __uint_as_float(f2tf32(x));
}

// ---------------- LayerNorm: warp per row, outputs tf32-rounded ------------
__global__ void ln_kernel(const float* __restrict__ x,
                          const float* __restrict__ g,
                          const float* __restrict__ b,
                          float* __restrict__ out) {
    const int row  = blockIdx.x*8 + (threadIdx.x >> 5);
    const int lane = threadIdx.x & 31;
    const float* px = x + (size_t)row*DD;
    float4 a = *reinterpret_cast<const float4*>(px + lane*4);
    float4 c = *reinterpret_cast<const float4*>(px + 128 + lane*4);
    float s1 = a.x+a.y+a.z+a.w + c.x+c.y+c.z+c.w;
    float s2 = a.x*a.x+a.y*a.y+a.z*a.z+a.w*a.w
             + c.x*c.x+c.y*c.y+c.z*c.z+c.w*c.w;
    #pragma unroll
    for (int o = 16; o > 0; o >>= 1) {
        s1 += __shfl_xor_sync(0xffffffffu, s1, o);
        s2 += __shfl_xor_sync(0xffffffffu, s2, o);
    }
    const float mu = s1 * (1.0f/DD);
    const float rs = rsqrtf(s2 * (1.0f/DD) - mu*mu + 1e-5f);
    float4 g0 = *reinterpret_cast<const float4*>(g + lane*4);
    float4 g1 = *reinterpret_cast<const float4*>(g + 128 + lane*4);
    float4 b0 = *reinterpret_cast<const float4*>(b + lane*4);
    float4 b1 = *reinterpret_cast<const float4*>(b + 128 + lane*4);
    float* po = out + (size_t)row*DD;
    *reinterpret_cast<float4*>(po + lane*4) = make_float4(
        rnd32((a.x-mu)*rs*g0.x + b0.x), rnd32((a.y-mu)*rs*g0.y + b0.y),
        rnd32((a.z-mu)*rs*g0.z + b0.z), rnd32((a.w-mu)*rs*g0.w + b0.w));
    *reinterpret_cast<float4*>(po + 128 + lane*4) = make_float4(
        rnd32((c.x-mu)*rs*g1.x + b1.x), rnd32((c.y-mu)*rs*g1.y + b1.y),
        rnd32((c.z-mu)*rs*g1.z + b1.z), rnd32((c.w-mu)*rs*g1.w + b1.w));
}

// ---------------- transpose (+tf32 round): per z, src[R][C] -> dst[C][R] ---
__global__ void transpose_rnd(const float* __restrict__ src, float* __restrict__ dst,
                              int ldS, int ldD,
                              long long sSh, long long sDh) {
    __shared__ float tile[32][33];
    const int z = blockIdx.z;
    src += (size_t)z*sSh;
    dst += (size_t)z*sDh;
    const int c0 = blockIdx.x*32, r0 = blockIdx.y*32;
    const int tx = threadIdx.x, ty = threadIdx.y;
    #pragma unroll
    for (int i = ty; i < 32; i += 8)
        tile[i][tx] = src[(size_t)(r0+i)*ldS + c0 + tx];
    __syncthreads();
    #pragma unroll
    for (int i = ty; i < 32; i += 8)
        dst[(size_t)(c0+i)*ldD + r0 + tx] = rnd32(tile[tx][i]);
}

// ---------------- V transpose: qkv V-part -> vT[bh][d][n] ------------------
__global__ void transpose_v(const float* __restrict__ qkv, float* __restrict__ vT) {
    __shared__ float tile[32][33];
    const int z = blockIdx.z, bb2 = z >> 3, hh2 = z & 7;
    const float* src = qkv + (size_t)bb2*NN_*QKV_N + 2*INNER + hh2*DD;
    float* dst = vT + (size_t)z*DD*NN_;
    const int d0 = blockIdx.x*32, n0 = blockIdx.y*32;
    const int tx = threadIdx.x, ty = threadIdx.y;
    #pragma unroll
    for (int i = ty; i < 32; i += 8)
        tile[i][tx] = src[(size_t)(n0+i)*QKV_N + d0 + tx];
    __syncthreads();
    #pragma unroll
    for (int i = ty; i < 32; i += 8)
        dst[(size_t)(d0+i)*NN_ + n0 + tx] = tile[tx][i];
}

// ---------------- tf32 GEMM: cp.async + ldmatrix, tile 128 x BN ------------
// C = f(alpha * A[M,K] @ op(B)); row-major; A (and B if TB) pre-rounded tf32.
// TB=false: B is [K,N] (reg-staged, rounded here; BN=64 only).
// TB=true:  B is [N,K] (cp.async).
// 8 warps (4r x 2c); warp tile 32 x (BN/2); K-chunk 32; double-buffered.
// Dynamic smem: As 2x(128x128B)=32768 @0, Bs 2x(BNx128B) @32768, redS after.
// EPI: 1 round, 2 bias+gelu+round, 3 bias+residual(no round),
//      4 rowsum-normalize+round [reads auxR, 8 partials], 5 exp+round [writes auxW]
template<int EPI, bool TB, int BN>
__global__ void __launch_bounds__(256)
gemm_tf32(const float* __restrict__ A, const float* __restrict__ B,
          const float* __restrict__ bias, const float* __restrict__ res,
          const float* __restrict__ auxR, float* __restrict__ auxW,
          float* __restrict__ C,
          int K, int lda, int ldb, int ldc,
          long long sAb, long long sAh, long long sBb, long long sBh,
          long long sCb, long long sCh, float alpha)
{
    constexpr int NF = BN / 32;          // b-frags (16-col) per warp
    constexpr int BUFB = BN * 128;       // bytes per B buffer
    constexpr int BUFA = 16384;          // bytes per A buffer (128 rows x 128B)

    const int bb = blockIdx.z >> 3;
    const int hh = blockIdx.z & 7;
    A += (size_t)bb*sAb + (size_t)hh*sAh;
    B += (size_t)bb*sBb + (size_t)hh*sBh;
    C += (size_t)bb*sCb + (size_t)hh*sCh;

    const int row0 = blockIdx.y * 128;
    const int col0 = blockIdx.x * BN;
    const int tid  = threadIdx.x;
    const int lane = tid & 31, wid = tid >> 5;
    const int wr = wid & 3, wc = wid >> 2;
    const int g  = lane >> 2, t4 = lane & 3;

    extern __shared__ char smraw[];
    const unsigned asBase = (unsigned)__cvta_generic_to_shared(smraw);
    const unsigned bsBase = asBase + 2*BUFA;
    float* redS = (float*)(smraw + 2*BUFA + 2*BUFB);   // [2][128]

    // ---- async loader geometry (16B chunks)
    const int rL  = tid >> 3;           // 0..31
    const int cL  = tid & 7;            // chunk 0..7
    const int csw = (cL ^ (rL & 7)) * 16;

    const float* pA = A + (size_t)(row0 + rL)*lda + cL*4;
    const float* pB = B + (size_t)(col0 + rL)*ldb + cL*4;   // TB only
    unsigned aW[4], bWT[NF];
    #pragma unroll
    for (int i = 0; i < 4; i++) aW[i] = asBase + (rL + 32*i)*128 + csw;
    #pragma unroll
    for (int i = 0; i < NF; i++) bWT[i] = bsBase + (rL + 32*i)*128 + csw;

    // ---- NN B loader (register staged; BN==64 path)
    const int nB  = tid & 63;
    const int kbB = (tid >> 6) * 8;
    float vbS[8];

    auto issue = [&](int kk, int buf) {
        #pragma unroll
        for (int i = 0; i < 4; i++) {
            const float* ga = pA + (size_t)i*32*lda + kk;
            asm volatile("cp.async.cg.shared.global [%0], [%1], 16;"
                         :: "r"(aW[i] + buf*BUFA), "l"(ga));
        }
        if (TB) {
            #pragma unroll
            for (int i = 0; i < NF; i++) {
                const float* gb = pB + (size_t)i*32*ldb + kk;
                asm volatile("cp.async.cg.shared.global [%0], [%1], 16;"
                             :: "r"(bWT[i] + buf*BUFB), "l"(gb));
            }
        }
        asm volatile("cp.async.commit_group;");
    };
    auto ldgB = [&](int kk) {
        if (!TB) {
            #pragma unroll
            for (int w = 0; w < 8; w++)
                vbS[w] = B[(size_t)(kk + kbB + w)*ldb + col0 + nB];
        }
    };
    auto stsB = [&](int buf) {
        if (!TB) {
            const int c0 = kbB >> 2;
            uint4 u0 = make_uint4(f2tf32(vbS[0]), f2tf32(vbS[1]),
                                  f2tf32(vbS[2]), f2tf32(vbS[3]));
            uint4 u1 = make_uint4(f2tf32(vbS[4]), f2tf32(vbS[5]),
                                  f2tf32(vbS[6]), f2tf32(vbS[7]));
            char* base = smraw + 2*BUFA + buf*BUFB + nB*128;
            *reinterpret_cast<uint4*>(base + (((c0  ) ^ (nB&7))<<4)) = u0;
            *reinterpret_cast<uint4*>(base + (((c0+1) ^ (nB&7))<<4)) = u1;
        }
    };

    // ---- ldmatrix address precompute
    const int ami   = lane >> 3;
    const int aHalf = ami >> 1;
    const int aRoff = ((ami & 1) << 3) + (lane & 7);
    int aM[2], aSw[2];
    #pragma unroll
    for (int mf = 0; mf < 2; mf++) {
        aM[mf]  = wr*32 + mf*16 + aRoff;
        aSw[mf] = aM[mf] & 7;
    }
    const int bHalf = (lane >> 3) & 1;
    const int bRoff = ((lane >> 4) << 3) + (lane & 7);
    int bN[NF], bSw[NF];
    #pragma unroll
    for (int nf = 0; nf < NF; nf++) {
        bN[nf]  = wc*(BN/2) + nf*16 + bRoff;
        bSw[nf] = bN[nf] & 7;
    }

    float acc[2][2*NF][4] = {};

    auto compute = [&](int buf) {
        const unsigned aBuf = asBase + buf*BUFA;
        const unsigned bBuf = bsBase + buf*BUFB;
        #pragma unroll
        for (int k8 = 0; k8 < 4; k8++) {
            uint4 af[2], bf[NF];
            #pragma unroll
            for (int mf = 0; mf < 2; mf++) {
                unsigned addr = aBuf + aM[mf]*128
                              + ((((k8<<1) + aHalf) ^ aSw[mf]) << 4);
                asm volatile(
                    "ldmatrix.sync.aligned.m8n8.x4.shared.b16 {%0,%1,%2,%3}, [%4];"
                    : "=r"(af[mf].x), "=r"(af[mf].y), "=r"(af[mf].z), "=r"(af[mf].w)
                    : "r"(addr));
            }
            #pragma unroll
            for (int nf = 0; nf < NF; nf++) {
                unsigned addr = bBuf + bN[nf]*128
                              + ((((k8<<1) + bHalf) ^ bSw[nf]) << 4);
                asm volatile(
                    "ldmatrix.sync.aligned.m8n8.x4.shared.b16 {%0,%1,%2,%3}, [%4];"
                    : "=r"(bf[nf].x), "=r"(bf[nf].y), "=r"(bf[nf].z), "=r"(bf[nf].w)
                    : "r"(addr));
            }
            #pragma unroll
            for (int m = 0; m < 2; m++)
                #pragma unroll
                for (int n = 0; n < 2*NF; n++) {
                    const unsigned b0 = (n & 1) ? bf[n>>1].z : bf[n>>1].x;
                    const unsigned b1 = (n & 1) ? bf[n>>1].w : bf[n>>1].y;
                    asm volatile(
                        "mma.sync.aligned.m16n8k8.row.col.f32.tf32.tf32.f32 "
                        "{%0,%1,%2,%3}, {%4,%5,%6,%7}, {%8,%9}, {%0,%1,%2,%3};"
                        : "+f"(acc[m][n][0]), "+f"(acc[m][n][1]),
                          "+f"(acc[m][n][2]), "+f"(acc[m][n][3])
                        : "r"(af[m].x), "r"(af[m].y), "r"(af[m].z), "r"(af[m].w),
                          "r"(b0), "r"(b1));
                }
        }
    };

    const int nch = K >> 5;
    issue(0, 0);
    ldgB(0);
    asm volatile("cp.async.wait_group 0;");
    stsB(0);
    __syncthreads();
    for (int ch = 0; ch < nch; ch++) {
        const int buf = ch & 1;
        const bool more = (ch + 1 < nch);
        if (more) { issue((ch + 1)*32, buf ^ 1); ldgB((ch + 1)*32); }
        compute(buf);
        if (more) {
            stsB(buf ^ 1);
            asm volatile("cp.async.wait_group 0;");
            __syncthreads();
        }
    }

    // EPI4: gather per-row normalizers (8 partials per row)
    if (EPI == 4) {
        if (tid < 128) {
            const float* p = auxR + ((size_t)blockIdx.z*1024 + row0 + tid)*16;
            float4 q0 = *reinterpret_cast<const float4*>(p);
            float4 q1 = *reinterpret_cast<const float4*>(p+4);
            redS[tid] = (q0.x+q0.y+q0.z+q0.w) + (q1.x+q1.y+q1.z+q1.w);
        }
        __syncthreads();
    }

    float rsums[2][2] = {};

    // epilogue
    #pragma unroll
    for (int m = 0; m < 2; m++) {
        const int rb = wr*32 + m*16 + g;
        #pragma unroll
        for (int n = 0; n < 2*NF; n++) {
            const int c = col0 + wc*(BN/2) + n*8 + 2*t4;
            #pragma unroll
            for (int h = 0; h < 2; h++) {
                const int rl = rb + h*8;
                const int r  = row0 + rl;
                float v0 = acc[m][n][2*h+0] * alpha;
                float v1 = acc[m][n][2*h+1] * alpha;
                if (EPI == 2 || EPI == 3) { v0 += bias[c]; v1 += bias[c+1]; }
                if (EPI == 2) {
                    v0 = 0.5f * v0 * (1.0f + erff(v0 * 0.70710678118654752f));
                    v1 = 0.5f * v1 * (1.0f + erff(v1 * 0.70710678118654752f));
                }
                if (EPI == 3) {
                    v0 += res[(size_t)r*ldc + c];
                    v1 += res[(size_t)r*ldc + c + 1];
                }
                if (EPI == 4) {
                    const float inv = 1.0f / redS[rl];
                    v0 *= inv; v1 *= inv;
                }
                if (EPI == 5) { v0 = __expf(v0); v1 = __expf(v1); }
                if (EPI != 3) { v0 = rnd32(v0); v1 = rnd32(v1); }
                if (EPI == 5) rsums[m][h] += v0 + v1;
                *reinterpret_cast<float2*>(&C[(size_t)r*ldc + c]) =
                    make_float2(v0, v1);
            }
        }
    }

    // EPI5: deterministic per-row partial sums
    if (EPI == 5) {
        #pragma unroll
        for (int m = 0; m < 2; m++)
            #pragma unroll
            for (int h = 0; h < 2; h++) {
                float s = rsums[m][h];
                s += __shfl_xor_sync(0xffffffffu, s, 1);
                s += __shfl_xor_sync(0xffffffffu, s, 2);
                if (t4 == 0) redS[wc*128 + wr*32 + m*16 + h*8 + g] = s;
            }
        __syncthreads();
        if (tid < 128) {
            float tot = redS[tid] + redS[128 + tid];
            auxW[((size_t)blockIdx.z*1024 + row0 + tid)*16 + blockIdx.x] = tot;
        }
    }
}

// smem sizes per BN
#define SMEM_BN128 (32768 + 2*128*128 + 1024)   // 66560
#define SMEM_BN64  (32768 + 2*64*128 + 1024)    // 50176

// ---------------- host launcher ----------------
extern "C" void kernel_launch(void* const* d_in, const int* in_sizes, int n_in,
                              void* d_out, int out_size) {
    const float* inputs = (const float*)d_in[0];
    const float* ln1_g  = (const float*)d_in[1];
    const float* ln1_b  = (const float*)d_in[2];
    const float* w_qkv  = (const float*)d_in[3];
    const float* w_proj = (const float*)d_in[4];
    const float* b_proj = (const float*)d_in[5];
    const float* ln2_g  = (const float*)d_in[6];
    const float* ln2_b  = (const float*)d_in[7];
    const float* w1     = (const float*)d_in[8];
    const float* b1     = (const float*)d_in[9];
    const float* w2     = (const float*)d_in[10];
    const float* b2     = (const float*)d_in[11];
    float* x = (float*)d_out;

    float *ph, *pqkv, *pscores, *pattn, *pmlp, *pspart, *pvT;
    float *pwqkvT, *pwprojT, *pw1T, *pw2T;
    cudaGetSymbolAddress((void**)&ph,      g_h);
    cudaGetSymbolAddress((void**)&pqkv,    g_qkv);
    cudaGetSymbolAddress((void**)&pscores, g_scores);
    cudaGetSymbolAddress((void**)&pattn,   g_attn);
    cudaGetSymbolAddress((void**)&pmlp,    g_mlp);
    cudaGetSymbolAddress((void**)&pspart,  g_spart);
    cudaGetSymbolAddress((void**)&pvT,     g_vT);
    cudaGetSymbolAddress((void**)&pwqkvT,  g_wqkvT);
    cudaGetSymbolAddress((void**)&pwprojT, g_wprojT);
    cudaGetSymbolAddress((void**)&pw1T,    g_w1T);
    cudaGetSymbolAddress((void**)&pw2T,    g_w2T);

    // raise dynamic smem limits (host-side, safe pre-capture)
    cudaFuncSetAttribute(gemm_tf32<1,true,128>,
        cudaFuncAttributeMaxDynamicSharedMemorySize, SMEM_BN128);
    cudaFuncSetAttribute(gemm_tf32<5,true,128>,
        cudaFuncAttributeMaxDynamicSharedMemorySize, SMEM_BN128);
    cudaFuncSetAttribute(gemm_tf32<2,true,128>,
        cudaFuncAttributeMaxDynamicSharedMemorySize, SMEM_BN128);
    cudaFuncSetAttribute(gemm_tf32<3,true,64>,
        cudaFuncAttributeMaxDynamicSharedMemorySize, SMEM_BN64);
    cudaFuncSetAttribute(gemm_tf32<4,true,64>,
        cudaFuncAttributeMaxDynamicSharedMemorySize, SMEM_BN64);

    cudaMemcpyAsync(x, inputs, (size_t)ROWS*DD*sizeof(float),
                    cudaMemcpyDeviceToDevice);

    const dim3 blk(256);
    const dim3 tblk(32, 8);

    // ---- one-time weight transposes (+tf32 rounding); z = layer
    transpose_rnd<<<dim3(QKV_N/32, DD/32, LNUM), tblk>>>(
        w_qkv, pwqkvT, QKV_N, DD,
        (long long)DD*QKV_N, (long long)QKV_N*DD);
    transpose_rnd<<<dim3(DD/32, INNER/32, LNUM), tblk>>>(
        w_proj, pwprojT, DD, INNER,
        (long long)INNER*DD, (long long)DD*INNER);
    transpose_rnd<<<dim3(MM/32, DD/32, LNUM), tblk>>>(
        w1, pw1T, MM, DD,
        (long long)DD*MM, (long long)MM*DD);
    transpose_rnd<<<dim3(DD/32, MM/32, LNUM), tblk>>>(
        w2, pw2T, DD, MM,
        (long long)MM*DD, (long long)DD*MM);

    for (int l = 0; l < LNUM; l++) {
        ln_kernel<<<ROWS/8, blk>>>(x, ln1_g + l*DD, ln1_b + l*DD, ph);

        // qkv = round(h @ w_qkvT^T)
        gemm_tf32<1,true,128><<<dim3(QKV_N/128, ROWS/128, 1), blk, SMEM_BN128>>>(
            ph, pwqkvT + (size_t)l*QKV_N*DD, nullptr, nullptr, nullptr, nullptr,
            pqkv, DD, DD, DD, QKV_N,
            0,0,0,0,0,0, 1.0f);

        // V^T per (b,h)
        transpose_v<<<dim3(DD/32, NN_/32, 64), tblk>>>(pqkv, pvT);

        // scoresExp = round(exp(SCALE * Q @ K^T)) + 8 partial rowsums/row
        gemm_tf32<5,true,128><<<dim3(1024/128, 1024/128, 64), blk, SMEM_BN128>>>(
            pqkv, pqkv + INNER, nullptr, nullptr, nullptr, pspart,
            pscores, DD, QKV_N, QKV_N, 1024,
            (long long)NN_*QKV_N, DD,
            (long long)NN_*QKV_N, DD,
            8LL*1024*1024, 1024LL*1024,
            SCALE_);

        // attn = round((scoresExp @ vT^T) / rowsum)   [TB: both cp.async]
        gemm_tf32<4,true,64><<<dim3(DD/64, 1024/128, 64), blk, SMEM_BN64>>>(
            pscores, pvT, nullptr, nullptr, pspart, nullptr,
            pattn, 1024, 1024, NN_, INNER,
            8LL*1024*1024, 1024LL*1024,
            8LL*DD*NN_,    (long long)DD*NN_,
            (long long)NN_*INNER, DD,
            1.0f);

        // x = x + attn @ w_projT^T + b_proj   [BN=64: 256 blocks]
        gemm_tf32<3,true,64><<<dim3(DD/64, ROWS/128, 1), blk, SMEM_BN64>>>(
            pattn, pwprojT + (size_t)l*DD*INNER, b_proj + l*DD, x, nullptr, nullptr,
            x, INNER, INNER, INNER, DD,
            0,0,0,0,0,0, 1.0f);

        ln_kernel<<<ROWS/8, blk>>>(x, ln2_g + l*DD, ln2_b + l*DD, ph);

        // hidden = round(gelu(h @ w1T^T + b1))
        gemm_tf32<2,true,128><<<dim3(MM/128, ROWS/128, 1), blk, SMEM_BN128>>>(
            ph, pw1T + (size_t)l*MM*DD, b1 + l*MM, nullptr, nullptr, nullptr,
            pmlp, DD, DD, DD, MM,
            0,0,0,0,0,0, 1.0f);

        // x = x + hidden @ w2T^T + b2   [BN=64: 256 blocks]
        gemm_tf32<3,true,64><<<dim3(DD/64, ROWS/128, 1), blk, SMEM_BN64>>>(
            pmlp, pw2T + (size_t)l*DD*MM, b2 + l*DD, x, nullptr, nullptr,
            x, MM, MM, MM, DD,
            0,0,0,0,0,0, 1.0f);
    }
}

// round 14
// speedup vs baseline: 1.4896x; 1.0305x over previous
#include <cuda_runtime.h>
#include <cuda_bf16.h>
#include <math.h>

// Problem constants
#define LNUM 4
#define DD   256
#define HH   8
#define INNER 2048
#define MM   1024
#define BB   8
#define NN_  1024
#define ROWS (BB*NN_)       // 8192
#define QKV_N (3*INNER)     // 6144
#define SCALE_ 0.0625f

// ---------------- device scratch ----------------
__device__ float g_h[(size_t)ROWS*DD];
__device__ float g_qkv[(size_t)ROWS*QKV_N];
__device__ float g_scores[(size_t)64*1024*1024];
__device__ float g_attn[(size_t)ROWS*INNER];
__device__ float g_mlp[(size_t)ROWS*MM];
__device__ float g_spart[(size_t)64*1024*16];   // per-row partial exp sums
__device__ float g_vT[(size_t)64*DD*NN_];       // V^T per (b,h): [256][1024]
__device__ float g_wqkvT[(size_t)LNUM*QKV_N*DD];
__device__ float g_wprojT[(size_t)LNUM*DD*INNER];
__device__ float g_w1T[(size_t)LNUM*MM*DD];
__device__ float g_w2T[(size_t)LNUM*DD*MM];

__device__ __forceinline__ unsigned f2tf32(float x) {
    unsigned r;
    asm("cvt.rna.tf32.f32 %0, %1;" : "=r"(r) : "f"(x));
    return r;
}
__device__ __forceinline__ float rnd32(float x) {
    return __uint_as_float(f2tf32(x));
}

// ---------------- LayerNorm: warp per row, outputs tf32-rounded ------------
__global__ void ln_kernel(const float* __restrict__ x,
                          const float* __restrict__ g,
                          const float* __restrict__ b,
                          float* __restrict__ out) {
    const int row  = blockIdx.x*8 + (threadIdx.x >> 5);
    const int lane = threadIdx.x & 31;
    const float* px = x + (size_t)row*DD;
    float4 a = *reinterpret_cast<const float4*>(px + lane*4);
    float4 c = *reinterpret_cast<const float4*>(px + 128 + lane*4);
    float s1 = a.x+a.y+a.z+a.w + c.x+c.y+c.z+c.w;
    float s2 = a.x*a.x+a.y*a.y+a.z*a.z+a.w*a.w
             + c.x*c.x+c.y*c.y+c.z*c.z+c.w*c.w;
    #pragma unroll
    for (int o = 16; o > 0; o >>= 1) {
        s1 += __shfl_xor_sync(0xffffffffu, s1, o);
        s2 += __shfl_xor_sync(0xffffffffu, s2, o);
    }
    const float mu = s1 * (1.0f/DD);
    const float rs = rsqrtf(s2 * (1.0f/DD) - mu*mu + 1e-5f);
    float4 g0 = *reinterpret_cast<const float4*>(g + lane*4);
    float4 g1 = *reinterpret_cast<const float4*>(g + 128 + lane*4);
    float4 b0 = *reinterpret_cast<const float4*>(b + lane*4);
    float4 b1 = *reinterpret_cast<const float4*>(b + 128 + lane*4);
    float* po = out + (size_t)row*DD;
    *reinterpret_cast<float4*>(po + lane*4) = make_float4(
        rnd32((a.x-mu)*rs*g0.x + b0.x), rnd32((a.y-mu)*rs*g0.y + b0.y),
        rnd32((a.z-mu)*rs*g0.z + b0.z), rnd32((a.w-mu)*rs*g0.w + b0.w));
    *reinterpret_cast<float4*>(po + 128 + lane*4) = make_float4(
        rnd32((c.x-mu)*rs*g1.x + b1.x), rnd32((c.y-mu)*rs*g1.y + b1.y),
        rnd32((c.z-mu)*rs*g1.z + b1.z), rnd32((c.w-mu)*rs*g1.w + b1.w));
}

// ---------------- transpose (+tf32 round): per z, src[R][C] -> dst[C][R] ---
__global__ void transpose_rnd(const float* __restrict__ src, float* __restrict__ dst,
                              int ldS, int ldD,
                              long long sSh, long long sDh) {
    __shared__ float tile[32][33];
    const int z = blockIdx.z;
    src += (size_t)z*sSh;
    dst += (size_t)z*sDh;
    const int c0 = blockIdx.x*32, r0 = blockIdx.y*32;
    const int tx = threadIdx.x, ty = threadIdx.y;
    #pragma unroll
    for (int i = ty; i < 32; i += 8)
        tile[i][tx] = src[(size_t)(r0+i)*ldS + c0 + tx];
    __syncthreads();
    #pragma unroll
    for (int i = ty; i < 32; i += 8)
        dst[(size_t)(c0+i)*ldD + r0 + tx] = rnd32(tile[tx][i]);
}

// ---------------- V transpose: qkv V-part -> vT[bh][d][n] ------------------
__global__ void transpose_v(const float* __restrict__ qkv, float* __restrict__ vT) {
    __shared__ float tile[32][33];
    const int z = blockIdx.z, bb2 = z >> 3, hh2 = z & 7;
    const float* src = qkv + (size_t)bb2*NN_*QKV_N + 2*INNER + hh2*DD;
    float* dst = vT + (size_t)z*DD*NN_;
    const int d0 = blockIdx.x*32, n0 = blockIdx.y*32;
    const int tx = threadIdx.x, ty = threadIdx.y;
    #pragma unroll
    for (int i = ty; i < 32; i += 8)
        tile[i][tx] = src[(size_t)(n0+i)*QKV_N + d0 + tx];
    __syncthreads();
    #pragma unroll
    for (int i = ty; i < 32; i += 8)
        dst[(size_t)(d0+i)*NN_ + n0 + tx] = tile[tx][i];
}

// ---------------- tf32 GEMM: all-TB cp.async + ldmatrix, 3-stage -----------
// C = f(alpha * A[M,K] @ B^T); A[M][K], B[N][K] row-major, both pre-rounded.
// 8 warps (4r x 2c); warp tile 32 x (BN/2); K-chunk 32; 3-stage pipeline.
// Dynamic smem: As 3x16384 @0, Bs 3x(BNx128B) after, redS after.
// EPI: 1 round, 2 bias+gelu+round, 3 bias+residual(no round),
//      4 rowsum-normalize+round [reads auxR, 8 partials], 5 exp+round [writes auxW]
template<int EPI, int BN>
__global__ void __launch_bounds__(256)
gemm_tf32(const float* __restrict__ A, const float* __restrict__ B,
          const float* __restrict__ bias, const float* __restrict__ res,
          const float* __restrict__ auxR, float* __restrict__ auxW,
          float* __restrict__ C,
          int K, int lda, int ldb, int ldc,
          long long sAb, long long sAh, long long sBb, long long sBh,
          long long sCb, long long sCh, float alpha)
{
    constexpr int NF = BN / 32;          // b-frags (16-col) per warp
    constexpr int BUFB = BN * 128;       // bytes per B stage
    constexpr int BUFA = 16384;          // bytes per A stage (128 rows x 128B)

    const int bb = blockIdx.z >> 3;
    const int hh = blockIdx.z & 7;
    A += (size_t)bb*sAb + (size_t)hh*sAh;
    B += (size_t)bb*sBb + (size_t)hh*sBh;
    C += (size_t)bb*sCb + (size_t)hh*sCh;

    const int row0 = blockIdx.y * 128;
    const int col0 = blockIdx.x * BN;
    const int tid  = threadIdx.x;
    const int lane = tid & 31, wid = tid >> 5;
    const int wr = wid & 3, wc = wid >> 2;
    const int g  = lane >> 2, t4 = lane & 3;

    extern __shared__ char smraw[];
    const unsigned asBase = (unsigned)__cvta_generic_to_shared(smraw);
    const unsigned bsBase = asBase + 3*BUFA;
    float* redS = (float*)(smraw + 3*BUFA + 3*BUFB);   // [2][128]

    // ---- async loader geometry (16B chunks)
    const int rL  = tid >> 3;           // 0..31
    const int cL  = tid & 7;            // chunk 0..7
    const int csw = (cL ^ (rL & 7)) * 16;

    const float* pA = A + (size_t)(row0 + rL)*lda + cL*4;
    const float* pB = B + (size_t)(col0 + rL)*ldb + cL*4;
    unsigned aW[4], bWT[NF];
    #pragma unroll
    for (int i = 0; i < 4; i++) aW[i] = asBase + (rL + 32*i)*128 + csw;
    #pragma unroll
    for (int i = 0; i < NF; i++) bWT[i] = bsBase + (rL + 32*i)*128 + csw;

    auto issue = [&](int kk, int buf) {
        #pragma unroll
        for (int i = 0; i < 4; i++) {
            const float* ga = pA + (size_t)i*32*lda + kk;
            asm volatile("cp.async.cg.shared.global [%0], [%1], 16;"
                         :: "r"(aW[i] + buf*BUFA), "l"(ga));
        }
        #pragma unroll
        for (int i = 0; i < NF; i++) {
            const float* gb = pB + (size_t)i*32*ldb + kk;
            asm volatile("cp.async.cg.shared.global [%0], [%1], 16;"
                         :: "r"(bWT[i] + buf*BUFB), "l"(gb));
        }
        asm volatile("cp.async.commit_group;");
    };

    // ---- ldmatrix address precompute
    const int ami   = lane >> 3;
    const int aHalf = ami >> 1;
    const int aRoff = ((ami & 1) << 3) + (lane & 7);
    int aM[2], aSw[2];
    #pragma unroll
    for (int mf = 0; mf < 2; mf++) {
        aM[mf]  = wr*32 + mf*16 + aRoff;
        aSw[mf] = aM[mf] & 7;
    }
    const int bHalf = (lane >> 3) & 1;
    const int bRoff = ((lane >> 4) << 3) + (lane & 7);
    int bN[NF], bSw[NF];
    #pragma unroll
    for (int nf = 0; nf < NF; nf++) {
        bN[nf]  = wc*(BN/2) + nf*16 + bRoff;
        bSw[nf] = bN[nf] & 7;
    }

    float acc[2][2*NF][4] = {};

    auto compute = [&](int buf) {
        const unsigned aBuf = asBase + buf*BUFA;
        const unsigned bBuf = bsBase + buf*BUFB;
        #pragma unroll
        for (int k8 = 0; k8 < 4; k8++) {
            uint4 af[2], bf[NF];
            #pragma unroll
            for (int mf = 0; mf < 2; mf++) {
                unsigned addr = aBuf + aM[mf]*128
                              + ((((k8<<1) + aHalf) ^ aSw[mf]) << 4);
                asm volatile(
                    "ldmatrix.sync.aligned.m8n8.x4.shared.b16 {%0,%1,%2,%3}, [%4];"
                    : "=r"(af[mf].x), "=r"(af[mf].y), "=r"(af[mf].z), "=r"(af[mf].w)
                    : "r"(addr));
            }
            #pragma unroll
            for (int nf = 0; nf < NF; nf++) {
                unsigned addr = bBuf + bN[nf]*128
                              + ((((k8<<1) + bHalf) ^ bSw[nf]) << 4);
                asm volatile(
                    "ldmatrix.sync.aligned.m8n8.x4.shared.b16 {%0,%1,%2,%3}, [%4];"
                    : "=r"(bf[nf].x), "=r"(bf[nf].y), "=r"(bf[nf].z), "=r"(bf[nf].w)
                    : "r"(addr));
            }
            #pragma unroll
            for (int m = 0; m < 2; m++)
                #pragma unroll
                for (int n = 0; n < 2*NF; n++) {
                    const unsigned b0 = (n & 1) ? bf[n>>1].z : bf[n>>1].x;
                    const unsigned b1 = (n & 1) ? bf[n>>1].w : bf[n>>1].y;
                    asm volatile(
                        "mma.sync.aligned.m16n8k8.row.col.f32.tf32.tf32.f32 "
                        "{%0,%1,%2,%3}, {%4,%5,%6,%7}, {%8,%9}, {%0,%1,%2,%3};"
                        : "+f"(acc[m][n][0]), "+f"(acc[m][n][1]),
                          "+f"(acc[m][n][2]), "+f"(acc[m][n][3])
                        : "r"(af[m].x), "r"(af[m].y), "r"(af[m].z), "r"(af[m].w),
                          "r"(b0), "r"(b1));
                }
        }
    };

    // ---- 3-stage pipeline ----
    const int nch = K >> 5;
    issue(0, 0);
    if (nch > 1) issue(32, 1);
    int bufC = 0;                // ch % 3
    for (int ch = 0; ch < nch; ch++) {
        if (ch < nch - 1) {
            asm volatile("cp.async.wait_group 1;");
        } else {
            asm volatile("cp.async.wait_group 0;");
        }
        __syncthreads();
        if (ch + 2 < nch) {
            int buf2 = bufC + 2; if (buf2 >= 3) buf2 -= 3;
            issue((ch + 2)*32, buf2);
        }
        compute(bufC);
        if (++bufC == 3) bufC = 0;
    }

    // EPI4: gather per-row normalizers (8 partials per row)
    if (EPI == 4) {
        if (tid < 128) {
            const float* p = auxR + ((size_t)blockIdx.z*1024 + row0 + tid)*16;
            float4 q0 = *reinterpret_cast<const float4*>(p);
            float4 q1 = *reinterpret_cast<const float4*>(p+4);
            redS[tid] = (q0.x+q0.y+q0.z+q0.w) + (q1.x+q1.y+q1.z+q1.w);
        }
        __syncthreads();
    }

    float rsums[2][2] = {};

    // epilogue
    #pragma unroll
    for (int m = 0; m < 2; m++) {
        const int rb = wr*32 + m*16 + g;
        #pragma unroll
        for (int n = 0; n < 2*NF; n++) {
            const int c = col0 + wc*(BN/2) + n*8 + 2*t4;
            #pragma unroll
            for (int h = 0; h < 2; h++) {
                const int rl = rb + h*8;
                const int r  = row0 + rl;
                float v0 = acc[m][n][2*h+0] * alpha;
                float v1 = acc[m][n][2*h+1] * alpha;
                if (EPI == 2 || EPI == 3) { v0 += bias[c]; v1 += bias[c+1]; }
                if (EPI == 2) {
                    v0 = 0.5f * v0 * (1.0f + erff(v0 * 0.70710678118654752f));
                    v1 = 0.5f * v1 * (1.0f + erff(v1 * 0.70710678118654752f));
                }
                if (EPI == 3) {
                    v0 += res[(size_t)r*ldc + c];
                    v1 += res[(size_t)r*ldc + c + 1];
                }
                if (EPI == 4) {
                    const float inv = 1.0f / redS[rl];
                    v0 *= inv; v1 *= inv;
                }
                if (EPI == 5) { v0 = __expf(v0); v1 = __expf(v1); }
                if (EPI != 3) { v0 = rnd32(v0); v1 = rnd32(v1); }
                if (EPI == 5) rsums[m][h] += v0 + v1;
                *reinterpret_cast<float2*>(&C[(size_t)r*ldc + c]) =
                    make_float2(v0, v1);
            }
        }
    }

    // EPI5: deterministic per-row partial sums
    if (EPI == 5) {
        #pragma unroll
        for (int m = 0; m < 2; m++)
            #pragma unroll
            for (int h = 0; h < 2; h++) {
                float s = rsums[m][h];
                s += __shfl_xor_sync(0xffffffffu, s, 1);
                s += __shfl_xor_sync(0xffffffffu, s, 2);
                if (t4 == 0) redS[wc*128 + wr*32 + m*16 + h*8 + g] = s;
            }
        __syncthreads();
        if (tid < 128) {
            float tot = redS[tid] + redS[128 + tid];
            auxW[((size_t)blockIdx.z*1024 + row0 + tid)*16 + blockIdx.x] = tot;
        }
    }
}

// smem sizes per BN (3 stages)
#define SMEM_BN128 (3*16384 + 3*128*128 + 1024)   // 99328
#define SMEM_BN64  (3*16384 + 3*64*128 + 1024)    // 74752

// ---------------- host launcher ----------------
extern "C" void kernel_launch(void* const* d_in, const int* in_sizes, int n_in,
                              void* d_out, int out_size) {
    const float* inputs = (const float*)d_in[0];
    const float* ln1_g  = (const float*)d_in[1];
    const float* ln1_b  = (const float*)d_in[2];
    const float* w_qkv  = (const float*)d_in[3];
    const float* w_proj = (const float*)d_in[4];
    const float* b_proj = (const float*)d_in[5];
    const float* ln2_g  = (const float*)d_in[6];
    const float* ln2_b  = (const float*)d_in[7];
    const float* w1     = (const float*)d_in[8];
    const float* b1     = (const float*)d_in[9];
    const float* w2     = (const float*)d_in[10];
    const float* b2     = (const float*)d_in[11];
    float* x = (float*)d_out;

    float *ph, *pqkv, *pscores, *pattn, *pmlp, *pspart, *pvT;
    float *pwqkvT, *pwprojT, *pw1T, *pw2T;
    cudaGetSymbolAddress((void**)&ph,      g_h);
    cudaGetSymbolAddress((void**)&pqkv,    g_qkv);
    cudaGetSymbolAddress((void**)&pscores, g_scores);
    cudaGetSymbolAddress((void**)&pattn,   g_attn);
    cudaGetSymbolAddress((void**)&pmlp,    g_mlp);
    cudaGetSymbolAddress((void**)&pspart,  g_spart);
    cudaGetSymbolAddress((void**)&pvT,     g_vT);
    cudaGetSymbolAddress((void**)&pwqkvT,  g_wqkvT);
    cudaGetSymbolAddress((void**)&pwprojT, g_wprojT);
    cudaGetSymbolAddress((void**)&pw1T,    g_w1T);
    cudaGetSymbolAddress((void**)&pw2T,    g_w2T);

    // raise dynamic smem limits (host-side, safe pre-capture)
    cudaFuncSetAttribute(gemm_tf32<1,128>,
        cudaFuncAttributeMaxDynamicSharedMemorySize, SMEM_BN128);
    cudaFuncSetAttribute(gemm_tf32<5,128>,
        cudaFuncAttributeMaxDynamicSharedMemorySize, SMEM_BN128);
    cudaFuncSetAttribute(gemm_tf32<2,128>,
        cudaFuncAttributeMaxDynamicSharedMemorySize, SMEM_BN128);
    cudaFuncSetAttribute(gemm_tf32<3,64>,
        cudaFuncAttributeMaxDynamicSharedMemorySize, SMEM_BN64);
    cudaFuncSetAttribute(gemm_tf32<4,64>,
        cudaFuncAttributeMaxDynamicSharedMemorySize, SMEM_BN64);

    cudaMemcpyAsync(x, inputs, (size_t)ROWS*DD*sizeof(float),
                    cudaMemcpyDeviceToDevice);

    const dim3 blk(256);
    const dim3 tblk(32, 8);

    // ---- one-time weight transposes (+tf32 rounding); z = layer
    transpose_rnd<<<dim3(QKV_N/32, DD/32, LNUM), tblk>>>(
        w_qkv, pwqkvT, QKV_N, DD,
        (long long)DD*QKV_N, (long long)QKV_N*DD);
    transpose_rnd<<<dim3(DD/32, INNER/32, LNUM), tblk>>>(
        w_proj, pwprojT, DD, INNER,
        (long long)INNER*DD, (long long)DD*INNER);
    transpose_rnd<<<dim3(MM/32, DD/32, LNUM), tblk>>>(
        w1, pw1T, MM, DD,
        (long long)DD*MM, (long long)MM*DD);
    transpose_rnd<<<dim3(DD/32, MM/32, LNUM), tblk>>>(
        w2, pw2T, DD, MM,
        (long long)MM*DD, (long long)DD*MM);

    for (int l = 0; l < LNUM; l++) {
        ln_kernel<<<ROWS/8, blk>>>(x, ln1_g + l*DD, ln1_b + l*DD, ph);

        // qkv = round(h @ w_qkvT^T)
        gemm_tf32<1,128><<<dim3(QKV_N/128, ROWS/128, 1), blk, SMEM_BN128>>>(
            ph, pwqkvT + (size_t)l*QKV_N*DD, nullptr, nullptr, nullptr, nullptr,
            pqkv, DD, DD, DD, QKV_N,
            0,0,0,0,0,0, 1.0f);

        // V^T per (b,h)
        transpose_v<<<dim3(DD/32, NN_/32, 64), tblk>>>(pqkv, pvT);

        // scoresExp = round(exp(SCALE * Q @ K^T)) + 8 partial rowsums/row
        gemm_tf32<5,128><<<dim3(1024/128, 1024/128, 64), blk, SMEM_BN128>>>(
            pqkv, pqkv + INNER, nullptr, nullptr, nullptr, pspart,
            pscores, DD, QKV_N, QKV_N, 1024,
            (long long)NN_*QKV_N, DD,
            (long long)NN_*QKV_N, DD,
            8LL*1024*1024, 1024LL*1024,
            SCALE_);

        // attn = round((scoresExp @ vT^T) / rowsum)
        gemm_tf32<4,64><<<dim3(DD/64, 1024/128, 64), blk, SMEM_BN64>>>(
            pscores, pvT, nullptr, nullptr, pspart, nullptr,
            pattn, 1024, 1024, NN_, INNER,
            8LL*1024*1024, 1024LL*1024,
            8LL*DD*NN_,    (long long)DD*NN_,
            (long long)NN_*INNER, DD,
            1.0f);

        // x = x + attn @ w_projT^T + b_proj
        gemm_tf32<3,64><<<dim3(DD/64, ROWS/128, 1), blk, SMEM_BN64>>>(
            pattn, pwprojT + (size_t)l*DD*INNER, b_proj + l*DD, x, nullptr, nullptr,
            x, INNER, INNER, INNER, DD,
            0,0,0,0,0,0, 1.0f);

        ln_kernel<<<ROWS/8, blk>>>(x, ln2_g + l*DD, ln2_b + l*DD, ph);

        // hidden = round(gelu(h @ w1T^T + b1))
        gemm_tf32<2,128><<<dim3(MM/128, ROWS/128, 1), blk, SMEM_BN128>>>(
            ph, pw1T + (size_t)l*MM*DD, b1 + l*MM, nullptr, nullptr, nullptr,
            pmlp, DD, DD, DD, MM,
            0,0,0,0,0,0, 1.0f);

        // x = x + hidden @ w2T^T + b2
        gemm_tf32<3,64><<<dim3(DD/64, ROWS/128, 1), blk, SMEM_BN64>>>(
            pmlp, pw2T + (size_t)l*DD*MM, b2 + l*DD, x, nullptr, nullptr,
            x, MM, MM, MM, DD,
            0,0,0,0,0,0, 1.0f);
    }
}

// round 16
// speedup vs baseline: 1.4938x; 1.0028x over previous
#include <cuda_runtime.h>
#include <cuda_bf16.h>
#include <math.h>

// Problem constants
#define LNUM 4
#define DD   256
#define HH   8
#define INNER 2048
#define MM   1024
#define BB   8
#define NN_  1024
#define ROWS (BB*NN_)       // 8192
#define QKV_N (3*INNER)     // 6144
#define SCALE_ 0.0625f

// ---------------- device scratch ----------------
__device__ float g_h[(size_t)ROWS*DD];
__device__ float g_qkv[(size_t)ROWS*QKV_N];
__device__ float g_scores[(size_t)64*1024*1024];
__device__ float g_attn[(size_t)ROWS*INNER];
__device__ float g_mlp[(size_t)ROWS*MM];
__device__ float g_spart[(size_t)64*1024*16];   // per-row partial exp sums
__device__ float g_vT[(size_t)64*DD*NN_];       // V^T per (b,h): [256][1024]
__device__ float g_wqkvT[(size_t)LNUM*QKV_N*DD];
__device__ float g_wprojT[(size_t)LNUM*DD*INNER];
__device__ float g_w1T[(size_t)LNUM*MM*DD];
__device__ float g_w2T[(size_t)LNUM*DD*MM];

__device__ __forceinline__ unsigned f2tf32(float x) {
    unsigned r;
    asm("cvt.rna.tf32.f32 %0, %1;" : "=r"(r) : "f"(x));
    return r;
}
__device__ __forceinline__ float rnd32(float x) {
    return __uint_as_float(f2tf32(x));
}

// ---------------- LayerNorm: warp per row, outputs tf32-rounded ------------
__global__ void ln_kernel(const float* __restrict__ x,
                          const float* __restrict__ g,
                          const float* __restrict__ b,
                          float* __restrict__ out) {
    const int row  = blockIdx.x*8 + (threadIdx.x >> 5);
    const int lane = threadIdx.x & 31;
    const float* px = x + (size_t)row*DD;
    float4 a = *reinterpret_cast<const float4*>(px + lane*4);
    float4 c = *reinterpret_cast<const float4*>(px + 128 + lane*4);
    float s1 = a.x+a.y+a.z+a.w + c.x+c.y+c.z+c.w;
    float s2 = a.x*a.x+a.y*a.y+a.z*a.z+a.w*a.w
             + c.x*c.x+c.y*c.y+c.z*c.z+c.w*c.w;
    #pragma unroll
    for (int o = 16; o > 0; o >>= 1) {
        s1 += __shfl_xor_sync(0xffffffffu, s1, o);
        s2 += __shfl_xor_sync(0xffffffffu, s2, o);
    }
    const float mu = s1 * (1.0f/DD);
    const float rs = rsqrtf(s2 * (1.0f/DD) - mu*mu + 1e-5f);
    float4 g0 = *reinterpret_cast<const float4*>(g + lane*4);
    float4 g1 = *reinterpret_cast<const float4*>(g + 128 + lane*4);
    float4 b0 = *reinterpret_cast<const float4*>(b + lane*4);
    float4 b1 = *reinterpret_cast<const float4*>(b + 128 + lane*4);
    float* po = out + (size_t)row*DD;
    *reinterpret_cast<float4*>(po + lane*4) = make_float4(
        rnd32((a.x-mu)*rs*g0.x + b0.x), rnd32((a.y-mu)*rs*g0.y + b0.y),
        rnd32((a.z-mu)*rs*g0.z + b0.z), rnd32((a.w-mu)*rs*g0.w + b0.w));
    *reinterpret_cast<float4*>(po + 128 + lane*4) = make_float4(
        rnd32((c.x-mu)*rs*g1.x + b1.x), rnd32((c.y-mu)*rs*g1.y + b1.y),
        rnd32((c.z-mu)*rs*g1.z + b1.z), rnd32((c.w-mu)*rs*g1.w + b1.w));
}

// ---------------- transpose (+tf32 round): per z, src[R][C] -> dst[C][R] ---
__global__ void transpose_rnd(const float* __restrict__ src, float* __restrict__ dst,
                              int ldS, int ldD,
                              long long sSh, long long sDh) {
    __shared__ float tile[32][33];
    const int z = blockIdx.z;
    src += (size_t)z*sSh;
    dst += (size_t)z*sDh;
    const int c0 = blockIdx.x*32, r0 = blockIdx.y*32;
    const int tx = threadIdx.x, ty = threadIdx.y;
    #pragma unroll
    for (int i = ty; i < 32; i += 8)
        tile[i][tx] = src[(size_t)(r0+i)*ldS + c0 + tx];
    __syncthreads();
    #pragma unroll
    for (int i = ty; i < 32; i += 8)
        dst[(size_t)(c0+i)*ldD + r0 + tx] = rnd32(tile[tx][i]);
}

// ---------------- V transpose: qkv V-part -> vT[bh][d][n] ------------------
__global__ void transpose_v(const float* __restrict__ qkv, float* __restrict__ vT) {
    __shared__ float tile[32][33];
    const int z = blockIdx.z, bb2 = z >> 3, hh2 = z & 7;
    const float* src = qkv + (size_t)bb2*NN_*QKV_N + 2*INNER + hh2*DD;
    float* dst = vT + (size_t)z*DD*NN_;
    const int d0 = blockIdx.x*32, n0 = blockIdx.y*32;
    const int tx = threadIdx.x, ty = threadIdx.y;
    #pragma unroll
    for (int i = ty; i < 32; i += 8)
        tile[i][tx] = src[(size_t)(n0+i)*QKV_N + d0 + tx];
    __syncthreads();
    #pragma unroll
    for (int i = ty; i < 32; i += 8)
        dst[(size_t)(d0+i)*NN_ + n0 + tx] = tile[tx][i];
}

// ---------------- tf32 GEMM: all-TB cp.async + ldmatrix, 3-stage -----------
// C = f(alpha * A[M,K] @ B^T); A[M][K], B[N][K] row-major, both pre-rounded.
// 8 warps (4r x 2c); warp tile 32 x (BN/2); K-chunk 32; 3-stage pipeline.
// Dynamic smem: As 3x16384 @0, Bs 3x(BNx128B) after, redS after.
// EPI: 1 round, 2 bias+gelu+round, 3 bias+residual(no round),
//      4 rowsum-normalize+round [reads auxR, 8 partials], 5 exp+round [writes auxW]
template<int EPI, int BN>
__global__ void __launch_bounds__(256)
gemm_tf32(const float* __restrict__ A, const float* __restrict__ B,
          const float* __restrict__ bias, const float* __restrict__ res,
          const float* __restrict__ auxR, float* __restrict__ auxW,
          float* __restrict__ C,
          int K, int lda, int ldb, int ldc,
          long long sAb, long long sAh, long long sBb, long long sBh,
          long long sCb, long long sCh, float alpha)
{
    constexpr int NF = BN / 32;          // b-frags (16-col) per warp
    constexpr int BUFB = BN * 128;       // bytes per B stage
    constexpr int BUFA = 16384;          // bytes per A stage (128 rows x 128B)

    const int bb = blockIdx.z >> 3;
    const int hh = blockIdx.z & 7;
    A += (size_t)bb*sAb + (size_t)hh*sAh;
    B += (size_t)bb*sBb + (size_t)hh*sBh;
    C += (size_t)bb*sCb + (size_t)hh*sCh;

    const int row0 = blockIdx.y * 128;
    const int col0 = blockIdx.x * BN;
    const int tid  = threadIdx.x;
    const int lane = tid & 31, wid = tid >> 5;
    const int wr = wid & 3, wc = wid >> 2;
    const int g  = lane >> 2, t4 = lane & 3;

    extern __shared__ char smraw[];
    const unsigned asBase = (unsigned)__cvta_generic_to_shared(smraw);
    const unsigned bsBase = asBase + 3*BUFA;
    float* redS = (float*)(smraw + 3*BUFA + 3*BUFB);   // [2][128]

    // ---- async loader geometry (16B chunks)
    const int rL  = tid >> 3;           // 0..31
    const int cL  = tid & 7;            // chunk 0..7
    const int csw = (cL ^ (rL & 7)) * 16;

    const float* pA = A + (size_t)(row0 + rL)*lda + cL*4;
    const float* pB = B + (size_t)(col0 + rL)*ldb + cL*4;
    unsigned aW[4], bWT[NF];
    #pragma unroll
    for (int i = 0; i < 4; i++) aW[i] = asBase + (rL + 32*i)*128 + csw;
    #pragma unroll
    for (int i = 0; i < NF; i++) bWT[i] = bsBase + (rL + 32*i)*128 + csw;

    auto issue = [&](int kk, int buf) {
        #pragma unroll
        for (int i = 0; i < 4; i++) {
            const float* ga = pA + (size_t)i*32*lda + kk;
            asm volatile("cp.async.cg.shared.global [%0], [%1], 16;"
                         :: "r"(aW[i] + buf*BUFA), "l"(ga));
        }
        #pragma unroll
        for (int i = 0; i < NF; i++) {
            const float* gb = pB + (size_t)i*32*ldb + kk;
            asm volatile("cp.async.cg.shared.global [%0], [%1], 16;"
                         :: "r"(bWT[i] + buf*BUFB), "l"(gb));
        }
        asm volatile("cp.async.commit_group;");
    };

    // ---- ldmatrix address precompute
    const int ami   = lane >> 3;
    const int aHalf = ami >> 1;
    const int aRoff = ((ami & 1) << 3) + (lane & 7);
    int aM[2], aSw[2];
    #pragma unroll
    for (int mf = 0; mf < 2; mf++) {
        aM[mf]  = wr*32 + mf*16 + aRoff;
        aSw[mf] = aM[mf] & 7;
    }
    const int bHalf = (lane >> 3) & 1;
    const int bRoff = ((lane >> 4) << 3) + (lane & 7);
    int bN[NF], bSw[NF];
    #pragma unroll
    for (int nf = 0; nf < NF; nf++) {
        bN[nf]  = wc*(BN/2) + nf*16 + bRoff;
        bSw[nf] = bN[nf] & 7;
    }

    float acc[2][2*NF][4] = {};

    auto compute = [&](int buf) {
        const unsigned aBuf = asBase + buf*BUFA;
        const unsigned bBuf = bsBase + buf*BUFB;
        #pragma unroll
        for (int k8 = 0; k8 < 4; k8++) {
            uint4 af[2], bf[NF];
            #pragma unroll
            for (int mf = 0; mf < 2; mf++) {
                unsigned addr = aBuf + aM[mf]*128
                              + ((((k8<<1) + aHalf) ^ aSw[mf]) << 4);
                asm volatile(
                    "ldmatrix.sync.aligned.m8n8.x4.shared.b16 {%0,%1,%2,%3}, [%4];"
                    : "=r"(af[mf].x), "=r"(af[mf].y), "=r"(af[mf].z), "=r"(af[mf].w)
                    : "r"(addr));
            }
            #pragma unroll
            for (int nf = 0; nf < NF; nf++) {
                unsigned addr = bBuf + bN[nf]*128
                              + ((((k8<<1) + bHalf) ^ bSw[nf]) << 4);
                asm volatile(
                    "ldmatrix.sync.aligned.m8n8.x4.shared.b16 {%0,%1,%2,%3}, [%4];"
                    : "=r"(bf[nf].x), "=r"(bf[nf].y), "=r"(bf[nf].z), "=r"(bf[nf].w)
                    : "r"(addr));
            }
            #pragma unroll
            for (int m = 0; m < 2; m++)
                #pragma unroll
                for (int n = 0; n < 2*NF; n++) {
                    const unsigned b0 = (n & 1) ? bf[n>>1].z : bf[n>>1].x;
                    const unsigned b1 = (n & 1) ? bf[n>>1].w : bf[n>>1].y;
                    asm volatile(
                        "mma.sync.aligned.m16n8k8.row.col.f32.tf32.tf32.f32 "
                        "{%0,%1,%2,%3}, {%4,%5,%6,%7}, {%8,%9}, {%0,%1,%2,%3};"
                        : "+f"(acc[m][n][0]), "+f"(acc[m][n][1]),
                          "+f"(acc[m][n][2]), "+f"(acc[m][n][3])
                        : "r"(af[m].x), "r"(af[m].y), "r"(af[m].z), "r"(af[m].w),
                          "r"(b0), "r"(b1));
                }
        }
    };

    // ---- 3-stage pipeline ----
    const int nch = K >> 5;
    issue(0, 0);
    if (nch > 1) issue(32, 1);
    int bufC = 0;                // ch % 3
    for (int ch = 0; ch < nch; ch++) {
        if (ch < nch - 1) {
            asm volatile("cp.async.wait_group 1;");
        } else {
            asm volatile("cp.async.wait_group 0;");
        }
        __syncthreads();
        if (ch + 2 < nch) {
            int buf2 = bufC + 2; if (buf2 >= 3) buf2 -= 3;
            issue((ch + 2)*32, buf2);
        }
        compute(bufC);
        if (++bufC == 3) bufC = 0;
    }

    // EPI4: gather per-row normalizers (8 partials per row)
    if (EPI == 4) {
        if (tid < 128) {
            const float* p = auxR + ((size_t)blockIdx.z*1024 + row0 + tid)*16;
            float4 q0 = *reinterpret_cast<const float4*>(p);
            float4 q1 = *reinterpret_cast<const float4*>(p+4);
            redS[tid] = (q0.x+q0.y+q0.z+q0.w) + (q1.x+q1.y+q1.z+q1.w);
        }
        __syncthreads();
    }

    float rsums[2][2] = {};

    // epilogue
    #pragma unroll
    for (int m = 0; m < 2; m++) {
        const int rb = wr*32 + m*16 + g;
        #pragma unroll
        for (int n = 0; n < 2*NF; n++) {
            const int c = col0 + wc*(BN/2) + n*8 + 2*t4;
            #pragma unroll
            for (int h = 0; h < 2; h++) {
                const int rl = rb + h*8;
                const int r  = row0 + rl;
                float v0 = acc[m][n][2*h+0] * alpha;
                float v1 = acc[m][n][2*h+1] * alpha;
                if (EPI == 2 || EPI == 3) { v0 += bias[c]; v1 += bias[c+1]; }
                if (EPI == 2) {
                    v0 = 0.5f * v0 * (1.0f + erff(v0 * 0.70710678118654752f));
                    v1 = 0.5f * v1 * (1.0f + erff(v1 * 0.70710678118654752f));
                }
                if (EPI == 3) {
                    v0 += res[(size_t)r*ldc + c];
                    v1 += res[(size_t)r*ldc + c + 1];
                }
                if (EPI == 4) {
                    const float inv = 1.0f / redS[rl];
                    v0 *= inv; v1 *= inv;
                }
                if (EPI == 5) { v0 = __expf(v0); v1 = __expf(v1); }
                if (EPI != 3) { v0 = rnd32(v0); v1 = rnd32(v1); }
                if (EPI == 5) rsums[m][h] += v0 + v1;
                *reinterpret_cast<float2*>(&C[(size_t)r*ldc + c]) =
                    make_float2(v0, v1);
            }
        }
    }

    // EPI5: deterministic per-row partial sums
    if (EPI == 5) {
        #pragma unroll
        for (int m = 0; m < 2; m++)
            #pragma unroll
            for (int h = 0; h < 2; h++) {
                float s = rsums[m][h];
                s += __shfl_xor_sync(0xffffffffu, s, 1);
                s += __shfl_xor_sync(0xffffffffu, s, 2);
                if (t4 == 0) redS[wc*128 + wr*32 + m*16 + h*8 + g] = s;
            }
        __syncthreads();
        if (tid < 128) {
            float tot = redS[tid] + redS[128 + tid];
            auxW[((size_t)blockIdx.z*1024 + row0 + tid)*16 + blockIdx.x] = tot;
        }
    }
}

// smem sizes per BN (3 stages)
#define SMEM_BN128 (3*16384 + 3*128*128 + 1024)   // 99328
#define SMEM_BN64  (3*16384 + 3*64*128 + 1024)    // 74752

// ---------------- host launcher ----------------
extern "C" void kernel_launch(void* const* d_in, const int* in_sizes, int n_in,
                              void* d_out, int out_size) {
    const float* inputs = (const float*)d_in[0];
    const float* ln1_g  = (const float*)d_in[1];
    const float* ln1_b  = (const float*)d_in[2];
    const float* w_qkv  = (const float*)d_in[3];
    const float* w_proj = (const float*)d_in[4];
    const float* b_proj = (const float*)d_in[5];
    const float* ln2_g  = (const float*)d_in[6];
    const float* ln2_b  = (const float*)d_in[7];
    const float* w1     = (const float*)d_in[8];
    const float* b1     = (const float*)d_in[9];
    const float* w2     = (const float*)d_in[10];
    const float* b2     = (const float*)d_in[11];
    float* x = (float*)d_out;

    float *ph, *pqkv, *pscores, *pattn, *pmlp, *pspart, *pvT;
    float *pwqkvT, *pwprojT, *pw1T, *pw2T;
    cudaGetSymbolAddress((void**)&ph,      g_h);
    cudaGetSymbolAddress((void**)&pqkv,    g_qkv);
    cudaGetSymbolAddress((void**)&pscores, g_scores);
    cudaGetSymbolAddress((void**)&pattn,   g_attn);
    cudaGetSymbolAddress((void**)&pmlp,    g_mlp);
    cudaGetSymbolAddress((void**)&pspart,  g_spart);
    cudaGetSymbolAddress((void**)&pvT,     g_vT);
    cudaGetSymbolAddress((void**)&pwqkvT,  g_wqkvT);
    cudaGetSymbolAddress((void**)&pwprojT, g_wprojT);
    cudaGetSymbolAddress((void**)&pw1T,    g_w1T);
    cudaGetSymbolAddress((void**)&pw2T,    g_w2T);

    // side stream + events for capture-safe fork/join (created once; reused)
    static cudaStream_t s2 = nullptr;
    static cudaEvent_t evRoot, evW, evFork[LNUM], evJoin[LNUM];
    if (!s2) {
        cudaStreamCreateWithFlags(&s2, cudaStreamNonBlocking);
        cudaEventCreateWithFlags(&evRoot, cudaEventDisableTiming);
        cudaEventCreateWithFlags(&evW,    cudaEventDisableTiming);
        for (int i = 0; i < LNUM; i++) {
            cudaEventCreateWithFlags(&evFork[i], cudaEventDisableTiming);
            cudaEventCreateWithFlags(&evJoin[i], cudaEventDisableTiming);
        }
    }

    // raise dynamic smem limits (host-side, safe pre-capture)
    cudaFuncSetAttribute(gemm_tf32<1,128>,
        cudaFuncAttributeMaxDynamicSharedMemorySize, SMEM_BN128);
    cudaFuncSetAttribute(gemm_tf32<5,128>,
        cudaFuncAttributeMaxDynamicSharedMemorySize, SMEM_BN128);
    cudaFuncSetAttribute(gemm_tf32<2,128>,
        cudaFuncAttributeMaxDynamicSharedMemorySize, SMEM_BN128);
    cudaFuncSetAttribute(gemm_tf32<3,64>,
        cudaFuncAttributeMaxDynamicSharedMemorySize, SMEM_BN64);
    cudaFuncSetAttribute(gemm_tf32<4,64>,
        cudaFuncAttributeMaxDynamicSharedMemorySize, SMEM_BN64);

    const dim3 blk(256);
    const dim3 tblk(32, 8);

    // ---- fork: weight transposes on side stream, overlapping memcpy + LN1
    cudaEventRecord(evRoot, 0);
    cudaStreamWaitEvent(s2, evRoot, 0);

    transpose_rnd<<<dim3(QKV_N/32, DD/32, LNUM), tblk, 0, s2>>>(
        w_qkv, pwqkvT, QKV_N, DD,
        (long long)DD*QKV_N, (long long)QKV_N*DD);
    transpose_rnd<<<dim3(DD/32, INNER/32, LNUM), tblk, 0, s2>>>(
        w_proj, pwprojT, DD, INNER,
        (long long)INNER*DD, (long long)DD*INNER);
    transpose_rnd<<<dim3(MM/32, DD/32, LNUM), tblk, 0, s2>>>(
        w1, pw1T, MM, DD,
        (long long)DD*MM, (long long)MM*DD);
    transpose_rnd<<<dim3(DD/32, MM/32, LNUM), tblk, 0, s2>>>(
        w2, pw2T, DD, MM,
        (long long)MM*DD, (long long)DD*MM);
    cudaEventRecord(evW, s2);

    cudaMemcpyAsync(x, inputs, (size_t)ROWS*DD*sizeof(float),
                    cudaMemcpyDeviceToDevice);

    for (int l = 0; l < LNUM; l++) {
        ln_kernel<<<ROWS/8, blk>>>(x, ln1_g + l*DD, ln1_b + l*DD, ph);

        if (l == 0) cudaStreamWaitEvent(0, evW, 0);   // weights ready

        // qkv = round(h @ w_qkvT^T)
        gemm_tf32<1,128><<<dim3(QKV_N/128, ROWS/128, 1), blk, SMEM_BN128>>>(
            ph, pwqkvT + (size_t)l*QKV_N*DD, nullptr, nullptr, nullptr, nullptr,
            pqkv, DD, DD, DD, QKV_N,
            0,0,0,0,0,0, 1.0f);

        // fork: V^T on side stream, hidden under the scores GEMM
        cudaEventRecord(evFork[l], 0);
        cudaStreamWaitEvent(s2, evFork[l], 0);
        transpose_v<<<dim3(DD/32, NN_/32, 64), tblk, 0, s2>>>(pqkv, pvT);
        cudaEventRecord(evJoin[l], s2);

        // scoresExp = round(exp(SCALE * Q @ K^T)) + 8 partial rowsums/row
        gemm_tf32<5,128><<<dim3(1024/128, 1024/128, 64), blk, SMEM_BN128>>>(
            pqkv, pqkv + INNER, nullptr, nullptr, nullptr, pspart,
            pscores, DD, QKV_N, QKV_N, 1024,
            (long long)NN_*QKV_N, DD,
            (long long)NN_*QKV_N, DD,
            8LL*1024*1024, 1024LL*1024,
            SCALE_);

        // join: vT must be ready before PV
        cudaStreamWaitEvent(0, evJoin[l], 0);

        // attn = round((scoresExp @ vT^T) / rowsum)
        gemm_tf32<4,64><<<dim3(DD/64, 1024/128, 64), blk, SMEM_BN64>>>(
            pscores, pvT, nullptr, nullptr, pspart, nullptr,
            pattn, 1024, 1024, NN_, INNER,
            8LL*1024*1024, 1024LL*1024,
            8LL*DD*NN_,    (long long)DD*NN_,
            (long long)NN_*INNER, DD,
            1.0f);

        // x = x + attn @ w_projT^T + b_proj
        gemm_tf32<3,64><<<dim3(DD/64, ROWS/128, 1), blk, SMEM_BN64>>>(
            pattn, pwprojT + (size_t)l*DD*INNER, b_proj + l*DD, x, nullptr, nullptr,
            x, INNER, INNER, INNER, DD,
            0,0,0,0,0,0, 1.0f);

        ln_kernel<<<ROWS/8, blk>>>(x, ln2_g + l*DD, ln2_b + l*DD, ph);

        // hidden = round(gelu(h @ w1T^T + b1))
        gemm_tf32<2,128><<<dim3(MM/128, ROWS/128, 1), blk, SMEM_BN128>>>(
            ph, pw1T + (size_t)l*MM*DD, b1 + l*MM, nullptr, nullptr, nullptr,
            pmlp, DD, DD, DD, MM,
            0,0,0,0,0,0, 1.0f);

        // x = x + hidden @ w2T^T + b2
        gemm_tf32<3,64><<<dim3(DD/64, ROWS/128, 1), blk, SMEM_BN64>>>(
            pmlp, pw2T + (size_t)l*DD*MM, b2 + l*DD, x, nullptr, nullptr,
            x, MM, MM, MM, DD,
            0,0,0,0,0,0, 1.0f);
    }
}